// round 12
// baseline (speedup 1.0000x reference)
#include <cuda_runtime.h>
#include <cuda_bf16.h>
#include <math.h>
#include <stdint.h>

#define B_  256
#define NV_ 35709
#define NR_ 107127          // NV*3
#define NF_ 70789
#define NK_ 68
#define CST 257

#define OUT_COLOR ((size_t)B_ * NR_)
#define OUT_LM    ((size_t)2 * B_ * NR_)
#define OUT_TRI   (OUT_LM + (size_t)B_ * NK_ * 3)

#define NPROJ (((NV_ + 31) / 32) * 8)    // 8928 proj blocks
#define NCOL  ((NV_ + 31) / 32)          // 1116 color blocks per group
#define NCOLA (8 * NCOL)                 // 8928 color blocks total
#define NT64  ((NR_ + 63) / 64)          // 1674 gemm row tiles
#define NTRI3 ((NF_ * 3 + 255) / 256)    // 830 tri-out blocks

// -------- device scratch --------
__device__ float g_mean[3];
__device__ float g_rot[B_ * 9];
__device__ uint2 g_Bpk[B_ * 112];                          // coeff hi/lo (chunk-permuted)
__device__ float g_face_shape[(size_t)NR_ * B_];           // [row][b]
__device__ float g_tex[(size_t)NR_ * B_];                  // [row][b]
__device__ int   g_tri[NF_ * 3];
__device__ int4  g_tri4[NF_];                              // padded tri for 1-LDG fetch
__device__ int   g_pbuf[NV_ * 8];
__device__ int   g_kp[NK_];

// bf16 hi/lo split of a float pair: hi = rn(a),rn(b); lo = rn(residual)
__device__ __forceinline__ void split2(float a, float b, uint32_t& hi, uint32_t& lo) {
    __nv_bfloat16 ah = __float2bfloat16_rn(a), bh = __float2bfloat16_rn(b);
    float ar = a - __bfloat162float(ah), br = b - __bfloat162float(bh);
    __nv_bfloat162 h = __halves2bfloat162(ah, bh);
    __nv_bfloat162 l = __halves2bfloat162(__float2bfloat16_rn(ar), __float2bfloat16_rn(br));
    hi = *reinterpret_cast<uint32_t*>(&h);
    lo = *reinterpret_cast<uint32_t*>(&l);
}

__device__ __forceinline__ uint2 load_split(const float* __restrict__ base,
                                            int kd, size_t row, int pair) {
    float2 v = *reinterpret_cast<const float2*>(base + row * kd + 2 * pair);
    uint32_t hi, lo;
    split2(v.x, v.y, hi, lo);
    return make_uint2(hi, lo);
}

__device__ __forceinline__ void mma_bf16(float* c,
    uint32_t a0, uint32_t a1, uint32_t a2, uint32_t a3,
    uint32_t b0, uint32_t b1)
{
    asm volatile(
        "mma.sync.aligned.m16n8k16.row.col.f32.bf16.bf16.f32 "
        "{%0,%1,%2,%3}, {%4,%5,%6,%7}, {%8,%9}, {%0,%1,%2,%3};"
        : "+f"(c[0]), "+f"(c[1]), "+f"(c[2]), "+f"(c[3])
        : "r"(a0), "r"(a1), "r"(a2), "r"(a3), "r"(b0), "r"(b1));
}

// ============================================================
__global__ void k_idx(const void* __restrict__ tri,
                      const void* __restrict__ pbuf,
                      const void* __restrict__ kp)
{
    const int* t32 = (const int*)tri;
    bool is64 = true;
    #pragma unroll
    for (int i = 1; i < 32; i += 2) is64 = is64 && (t32[i] == 0);

    int gid = blockIdx.x * blockDim.x + threadIdx.x;
    int stride = gridDim.x * blockDim.x;
    if (is64) {
        const long long* a = (const long long*)tri;
        for (int i = gid; i < NF_ * 3; i += stride) g_tri[i] = (int)a[i];
        for (int i = gid; i < NF_; i += stride)
            g_tri4[i] = make_int4((int)a[3 * i], (int)a[3 * i + 1], (int)a[3 * i + 2], 0);
        const long long* b = (const long long*)pbuf;
        for (int i = gid; i < NV_ * 8; i += stride) g_pbuf[i] = (int)b[i];
        const long long* c = (const long long*)kp;
        for (int i = gid; i < NK_; i += stride) g_kp[i] = (int)c[i];
    } else {
        const int* a = (const int*)tri;
        for (int i = gid; i < NF_ * 3; i += stride) g_tri[i] = a[i];
        for (int i = gid; i < NF_; i += stride)
            g_tri4[i] = make_int4(a[3 * i], a[3 * i + 1], a[3 * i + 2], 0);
        const int* b = (const int*)pbuf;
        for (int i = gid; i < NV_ * 8; i += stride) g_pbuf[i] = b[i];
        const int* c = (const int*)kp;
        for (int i = gid; i < NK_; i += stride) g_kp[i] = c[i];
    }
}

// ============================================================
__global__ void k_prep(const float* __restrict__ coeff,
                       const float* __restrict__ meanshape)
{
    __shared__ float rx[256], ry[256], rz[256];
    int t = threadIdx.x;
    float s0 = 0.f, s1 = 0.f, s2 = 0.f;
    for (int v = t; v < NV_; v += 256) {
        s0 += meanshape[v * 3 + 0];
        s1 += meanshape[v * 3 + 1];
        s2 += meanshape[v * 3 + 2];
    }
    rx[t] = s0; ry[t] = s1; rz[t] = s2;
    __syncthreads();
    for (int off = 128; off > 0; off >>= 1) {
        if (t < off) { rx[t] += rx[t + off]; ry[t] += ry[t + off]; rz[t] += rz[t + off]; }
        __syncthreads();
    }
    if (t == 0) {
        g_mean[0] = rx[0] / (float)NV_;
        g_mean[1] = ry[0] / (float)NV_;
        g_mean[2] = rz[0] / (float)NV_;
    }
    float ax = coeff[t * CST + 224], ay = coeff[t * CST + 225], az = coeff[t * CST + 226];
    float sx = sinf(ax), cx = cosf(ax);
    float sy = sinf(ay), cy = cosf(ay);
    float sz = sinf(az), cz = cosf(az);
    float* M = g_rot + t * 9;
    M[0] = cz * cy;  M[1] = cz * sy * sx - sz * cx;  M[2] = cz * sy * cx + sz * sx;
    M[3] = sz * cy;  M[4] = sz * sy * sx + cz * cx;  M[5] = sz * sy * cx - cz * sx;
    M[6] = -sy;      M[7] = cy * sx;                 M[8] = cy * cx;
}

// ============================================================
__global__ void k_coeffB(const float* __restrict__ coeff)
{
    int b = blockIdx.x, c = threadIdx.x;  // c: 0..111
    float x = coeff[b * CST + 2 * c];
    float y = coeff[b * CST + 2 * c + 1];
    uint32_t hi, lo;
    split2(x, y, hi, lo);
    int w = c & 7;
    int pos = (c & ~7) + ((w & 3) * 2 + (w >> 2));
    g_Bpk[b * 112 + pos] = make_uint2(hi, lo);
}

// ============================================================
// k_hmma: bf16-split tensor-core GEMM (round-9 config).
// blockIdx.x < NT64: face_shape (K=144); else face_texture (K=80).
// Warp tile m32 x n64; block 64 rows x 256 batches.
// ============================================================
__global__ __launch_bounds__(256, 2) void k_hmma(
    const float* __restrict__ idBase, const float* __restrict__ exBase,
    const float* __restrict__ texBase,
    const float* __restrict__ meanshape, const float* __restrict__ meantex)
{
    int t = threadIdx.x;
    int w = t >> 5, lane = t & 31;
    int g = lane >> 2, tig = lane & 3;
    int wm = w & 1, wn = w >> 1;
    bool is_shape = (blockIdx.x < NT64);
    int tile = is_shape ? blockIdx.x : (blockIdx.x - NT64);
    int r0 = tile * 64;
    int nch = is_shape ? 9 : 5;
    int kboff = is_shape ? 0 : 72;

    int rw0 = r0 + wm * 32 + g;
    int rows[4] = {rw0, rw0 + 8, rw0 + 16, rw0 + 24};
    size_t lrows[4];
    #pragma unroll
    for (int s = 0; s < 4; ++s)
        lrows[s] = (size_t)(rows[s] < NR_ ? rows[s] : NR_ - 1);
    int n0 = wn * 64;

    float acc[8][8];
    #pragma unroll
    for (int j = 0; j < 8; ++j)
        #pragma unroll
        for (int q = 0; q < 8; ++q) acc[j][q] = 0.f;

    for (int c = 0; c < nch; ++c) {
        int kw = c * 8;
        const float* ab;
        int kd, poff;
        if (is_shape) {
            if (c < 5) { ab = idBase; kd = 80; poff = 0; }
            else       { ab = exBase; kd = 64; poff = 40; }
        } else       { ab = texBase; kd = 80; poff = 0; }
        int p0 = kw + tig - poff;
        uint2 a00 = load_split(ab, kd, lrows[0], p0);
        uint2 a01 = load_split(ab, kd, lrows[1], p0);
        uint2 a02 = load_split(ab, kd, lrows[0], p0 + 4);
        uint2 a03 = load_split(ab, kd, lrows[1], p0 + 4);
        uint2 a10 = load_split(ab, kd, lrows[2], p0);
        uint2 a11 = load_split(ab, kd, lrows[3], p0);
        uint2 a12 = load_split(ab, kd, lrows[2], p0 + 4);
        uint2 a13 = load_split(ab, kd, lrows[3], p0 + 4);

        const uint2* bbase = g_Bpk + (size_t)(n0 + g) * 112 + kboff + kw + 2 * tig;
        #pragma unroll
        for (int j = 0; j < 8; ++j) {
            uint4 bv = *reinterpret_cast<const uint4*>(bbase + (size_t)j * 8 * 112);
            mma_bf16(&acc[j][0], a00.x, a01.x, a02.x, a03.x, bv.x, bv.z);
            mma_bf16(&acc[j][0], a00.x, a01.x, a02.x, a03.x, bv.y, bv.w);
            mma_bf16(&acc[j][0], a00.y, a01.y, a02.y, a03.y, bv.x, bv.z);
            mma_bf16(&acc[j][4], a10.x, a11.x, a12.x, a13.x, bv.x, bv.z);
            mma_bf16(&acc[j][4], a10.x, a11.x, a12.x, a13.x, bv.y, bv.w);
            mma_bf16(&acc[j][4], a10.y, a11.y, a12.y, a13.y, bv.x, bv.z);
        }
    }

    float addv[4];
    float* dst;
    if (is_shape) {
        #pragma unroll
        for (int s = 0; s < 4; ++s)
            addv[s] = (rows[s] < NR_) ? meanshape[rows[s]] - g_mean[rows[s] % 3] : 0.f;
        dst = g_face_shape;
    } else {
        #pragma unroll
        for (int s = 0; s < 4; ++s)
            addv[s] = (rows[s] < NR_) ? meantex[rows[s]] : 0.f;
        dst = g_tex;
    }
    #pragma unroll
    for (int j = 0; j < 8; ++j) {
        int col = n0 + j * 8 + 2 * tig;
        #pragma unroll
        for (int s = 0; s < 4; ++s) {
            if (rows[s] < NR_) {
                int base = (s >> 1) * 4 + (s & 1) * 2;
                *reinterpret_cast<float2*>(dst + (size_t)rows[s] * B_ + col) =
                    make_float2(acc[j][base] + addv[s], acc[j][base + 1] + addv[s]);
            }
        }
    }
}

// ============================================================
// mega-kernel device blocks
// ============================================================
__device__ __forceinline__ void proj_block(
    int bx, const float* __restrict__ coeff, float* __restrict__ dout, float* sm)
{
    float* s    = sm;          // [96][33]
    float* srot = sm + 3200;   // [32][12]
    int t = threadIdx.x;
    int g = bx % 8;
    int v0 = (bx / 8) * 32;
    int r0 = v0 * 3;

    for (int idx = t; idx < 32 * 12; idx += 256) {
        int b_l = idx / 12, k = idx % 12;
        int b = g * 32 + b_l;
        srot[b_l * 12 + k] = (k < 9) ? g_rot[b * 9 + k] : coeff[b * CST + 254 + (k - 9)];
    }
    #pragma unroll
    for (int it = 0; it < 12; it++) {
        int idx = t + it * 256;
        int row = idx >> 5, b_l = idx & 31;
        s[row * 33 + b_l] = (r0 + row < NR_) ?
            g_face_shape[(size_t)(r0 + row) * B_ + g * 32 + b_l] : 0.f;
    }
    __syncthreads();

    int b_l = t >> 3, j = t & 7;
    int b = g * 32 + b_l;
    float m0 = srot[b_l * 12 + 0], m1 = srot[b_l * 12 + 1], m2 = srot[b_l * 12 + 2];
    float m3 = srot[b_l * 12 + 3], m4 = srot[b_l * 12 + 4], m5 = srot[b_l * 12 + 5];
    float m6 = srot[b_l * 12 + 6], m7 = srot[b_l * 12 + 7], m8 = srot[b_l * 12 + 8];
    float tx = srot[b_l * 12 + 9], ty = srot[b_l * 12 + 10], tz = srot[b_l * 12 + 11];
    #pragma unroll
    for (int w = 0; w < 4; w++) {
        int v_l = j * 4 + w;
        int v = v0 + v_l;
        if (v < NV_) {
            float x = s[(v_l * 3 + 0) * 33 + b_l];
            float y = s[(v_l * 3 + 1) * 33 + b_l];
            float z = s[(v_l * 3 + 2) * 33 + b_l];
            float* o = dout + (size_t)b * NR_ + (size_t)v * 3;
            o[0] = fmaf(m0, x, fmaf(m1, y, fmaf(m2, z, tx)));
            o[1] = fmaf(m3, x, fmaf(m4, y, fmaf(m5, z, ty)));
            o[2] = fmaf(m6, x, fmaf(m7, y, fmaf(m8, z, tz)));
        }
    }
}

// color with inline face-normal computation (no face_norm buffer)
__device__ __forceinline__ void color_direct(
    int bx, const float* __restrict__ coeff,
    float* __restrict__ dout, float* sm)
{
    const float A0C0   = 0.88622692545275801f;
    const float A1C1   = 1.77245385090551603f;
    const float A2C2   = 2.42703222385900050f;
    const float A2C2D0 = 0.70062326950125306f;
    const float A2C2H  = 1.21351611192950025f;

    float* sc = sm;          // [96][33]
    float* sg = sm + 3200;   // [32][27]
    int t = threadIdx.x;
    int g = bx / NCOL;
    int v0 = (bx % NCOL) * 32;

    for (int idx = t; idx < 32 * 27; idx += 256) {
        int b_l = idx / 27, kk = idx % 27;
        int k = kk / 3, c = kk % 3;
        float gv = coeff[(size_t)(g * 32 + b_l) * CST + 227 + c * 9 + k];
        if (k == 0) gv += 0.8f;
        sg[b_l * 27 + k * 3 + c] = gv;
    }
    __syncthreads();

    int vslot = t >> 5, b_l = t & 31;
    int b = g * 32 + b_l;
    const float* fs = g_face_shape;
    #pragma unroll
    for (int it = 0; it < 4; it++) {
        int v_l = vslot + it * 8;
        int v = v0 + v_l;
        if (v < NV_) {
            const int4* pb4 = reinterpret_cast<const int4*>(g_pbuf + v * 8);
            int4 pa = pb4[0], pbv = pb4[1];
            int f[8] = {pa.x, pa.y, pa.z, pa.w, pbv.x, pbv.y, pbv.z, pbv.w};
            float sx = 0.f, sy = 0.f, sz = 0.f;
            #pragma unroll
            for (int i = 0; i < 8; i++) {
                int fid = f[i];
                if (fid < NF_) {
                    int4 tr = g_tri4[fid];
                    size_t o0 = (size_t)(3 * tr.x) * B_ + b;
                    size_t o1 = (size_t)(3 * tr.y) * B_ + b;
                    size_t o2 = (size_t)(3 * tr.z) * B_ + b;
                    float v1x = fs[o0], v1y = fs[o0 + B_], v1z = fs[o0 + 2 * B_];
                    float v2x = fs[o1], v2y = fs[o1 + B_], v2z = fs[o1 + 2 * B_];
                    float v3x = fs[o2], v3y = fs[o2 + B_], v3z = fs[o2 + 2 * B_];
                    float e1x = v1x - v2x, e1y = v1y - v2y, e1z = v1z - v2z;
                    float e2x = v2x - v3x, e2y = v2y - v3y, e2z = v2z - v3z;
                    sx += e1y * e2z - e1z * e2y;
                    sy += e1z * e2x - e1x * e2z;
                    sz += e1x * e2y - e1y * e2x;
                }
            }
            float inv = rsqrtf(sx * sx + sy * sy + sz * sz);
            float nx = sx * inv, ny = sy * inv, nz = sz * inv;

            float Y[9];
            Y[0] = A0C0;
            Y[1] = -A1C1 * ny;
            Y[2] =  A1C1 * nz;
            Y[3] = -A1C1 * nx;
            Y[4] =  A2C2 * nx * ny;
            Y[5] = -A2C2 * ny * nz;
            Y[6] =  A2C2D0 * (3.f * nz * nz - 1.f);
            Y[7] = -A2C2 * nx * nz;
            Y[8] =  A2C2H * (nx * nx - ny * ny);

            const float* tx = g_tex + (size_t)(v * 3) * B_ + b;
            #pragma unroll
            for (int c = 0; c < 3; c++) {
                float l = 0.f;
                #pragma unroll
                for (int k = 0; k < 9; k++) l = fmaf(Y[k], sg[b_l * 27 + k * 3 + c], l);
                float col = tx[(size_t)c * B_] * l * (1.f / 255.f);
                sc[(v_l * 3 + c) * 33 + b_l] = fminf(fmaxf(col, 0.f), 1.f);
            }
        }
    }
    __syncthreads();

    int b_l2 = t >> 3, j = t & 7;
    int b2 = g * 32 + b_l2;
    #pragma unroll
    for (int w = 0; w < 4; w++) {
        int v_l = j * 4 + w;
        int v = v0 + v_l;
        if (v < NV_) {
            float* o = dout + OUT_COLOR + (size_t)b2 * NR_ + (size_t)v * 3;
            o[0] = sc[(v_l * 3 + 0) * 33 + b_l2];
            o[1] = sc[(v_l * 3 + 1) * 33 + b_l2];
            o[2] = sc[(v_l * 3 + 2) * 33 + b_l2];
        }
    }
}

// landmarks: recompute projection for keypoint vertices (bitwise-identical fmaf chain)
__device__ __forceinline__ void lm_block(int k, const float* __restrict__ coeff,
                                         float* __restrict__ dout)
{
    int b = threadIdx.x;
    int v = g_kp[k];
    const float* fs = g_face_shape;
    float x = fs[(size_t)(3 * v + 0) * B_ + b];
    float y = fs[(size_t)(3 * v + 1) * B_ + b];
    float z = fs[(size_t)(3 * v + 2) * B_ + b];
    const float* M = g_rot + b * 9;
    float tx = coeff[b * CST + 254], ty = coeff[b * CST + 255], tz = coeff[b * CST + 256];
    float* o = dout + OUT_LM + ((size_t)b * NK_ + k) * 3;
    o[0] = fmaf(M[0], x, fmaf(M[1], y, fmaf(M[2], z, tx)));
    o[1] = fmaf(M[3], x, fmaf(M[4], y, fmaf(M[5], z, ty)));
    o[2] = fmaf(M[6], x, fmaf(M[7], y, fmaf(M[8], z, tz)));
}

__device__ __forceinline__ void triout_block(int bx, float* __restrict__ dout)
{
    int q = bx * 256 + threadIdx.x;
    if (q < NF_ * 3) dout[OUT_TRI + q] = (float)g_tri[q];
}

// ============================================================
// k_mega: colorAll (group-ordered) + proj + landmarks + tri-out
// ============================================================
__global__ __launch_bounds__(256, 3) void k_mega(
    const float* __restrict__ coeff, float* __restrict__ dout)
{
    __shared__ __align__(16) float sm[4096];
    int bx = blockIdx.x;
    if (bx < NCOLA) {
        color_direct(bx, coeff, dout, sm);
    } else if (bx < NCOLA + NPROJ) {
        proj_block(bx - NCOLA, coeff, dout, sm);
    } else if (bx < NCOLA + NPROJ + NK_) {
        lm_block(bx - NCOLA - NPROJ, coeff, dout);
    } else {
        triout_block(bx - NCOLA - NPROJ - NK_, dout);
    }
}

// ============================================================
extern "C" void kernel_launch(void* const* d_in, const int* in_sizes, int n_in,
                              void* d_out, int out_size)
{
    (void)in_sizes; (void)n_in; (void)out_size;
    const float* coeff     = (const float*)d_in[0];
    const float* meanshape = (const float*)d_in[1];
    const float* idBase    = (const float*)d_in[2];
    const float* exBase    = (const float*)d_in[3];
    const float* meantex   = (const float*)d_in[4];
    const float* texBase   = (const float*)d_in[5];
    const void*  tri       = d_in[6];
    const void*  pbuf      = d_in[7];
    const void*  kp        = d_in[8];
    float* dout = (float*)d_out;

    k_idx    <<<128, 256>>>(tri, pbuf, kp);
    k_prep   <<<1, 256>>>(coeff, meanshape);
    k_coeffB <<<256, 112>>>(coeff);
    k_hmma   <<<2 * NT64, 256>>>(idBase, exBase, texBase, meanshape, meantex);
    k_mega   <<<NCOLA + NPROJ + NK_ + NTRI3, 256>>>(coeff, dout);
}

// round 13
// speedup vs baseline: 1.0033x; 1.0033x over previous
#include <cuda_runtime.h>
#include <cuda_bf16.h>
#include <math.h>
#include <stdint.h>

#define B_  256
#define NV_ 35709
#define NR_ 107127          // NV*3
#define NF_ 70789
#define NK_ 68
#define CST 257

#define OUT_COLOR ((size_t)B_ * NR_)
#define OUT_LM    ((size_t)2 * B_ * NR_)
#define OUT_TRI   (OUT_LM + (size_t)B_ * NK_ * 3)

#define NPROJ (((NV_ + 31) / 32) * 8)    // 8928 proj blocks
#define NFN   ((NF_ + 1 + 31) / 32)      // 2213 fn blocks per group (32 faces/block)
#define NCOL  ((NV_ + 31) / 32)          // 1116 color blocks per group
#define NT64  ((NR_ + 63) / 64)          // 1674 shape-gemm row tiles
#define NT32  ((NR_ + 31) / 32)          // 3348 tex-gemm row tiles (small)

// -------- device scratch --------
__device__ float g_mean[3];
__device__ float g_rot[B_ * 9];
__device__ uint2 g_Bpk[B_ * 112];                          // coeff hi/lo (chunk-permuted)
__device__ float g_face_shape[(size_t)NR_ * B_];           // [row][b]
__device__ float g_tex[(size_t)NR_ * B_];                  // [row][b]
__device__ float g_face_norm[(size_t)(NF_ + 1) * 3 * B_];  // [face*3+d][b]
__device__ int   g_tri[NF_ * 3];
__device__ int   g_pbuf[NV_ * 8];
__device__ int   g_kp[NK_];

// bf16 hi/lo split of a float pair: hi = rn(a),rn(b); lo = rn(residual)
__device__ __forceinline__ void split2(float a, float b, uint32_t& hi, uint32_t& lo) {
    __nv_bfloat16 ah = __float2bfloat16_rn(a), bh = __float2bfloat16_rn(b);
    float ar = a - __bfloat162float(ah), br = b - __bfloat162float(bh);
    __nv_bfloat162 h = __halves2bfloat162(ah, bh);
    __nv_bfloat162 l = __halves2bfloat162(__float2bfloat16_rn(ar), __float2bfloat16_rn(br));
    hi = *reinterpret_cast<uint32_t*>(&h);
    lo = *reinterpret_cast<uint32_t*>(&l);
}

__device__ __forceinline__ uint2 load_split(const float* __restrict__ base,
                                            int kd, size_t row, int pair) {
    float2 v = *reinterpret_cast<const float2*>(base + row * kd + 2 * pair);
    uint32_t hi, lo;
    split2(v.x, v.y, hi, lo);
    return make_uint2(hi, lo);
}

__device__ __forceinline__ void mma_bf16(float* c,
    uint32_t a0, uint32_t a1, uint32_t a2, uint32_t a3,
    uint32_t b0, uint32_t b1)
{
    asm volatile(
        "mma.sync.aligned.m16n8k16.row.col.f32.bf16.bf16.f32 "
        "{%0,%1,%2,%3}, {%4,%5,%6,%7}, {%8,%9}, {%0,%1,%2,%3};"
        : "+f"(c[0]), "+f"(c[1]), "+f"(c[2]), "+f"(c[3])
        : "r"(a0), "r"(a1), "r"(a2), "r"(a3), "r"(b0), "r"(b1));
}

// ============================================================
__global__ void k_idx(const void* __restrict__ tri,
                      const void* __restrict__ pbuf,
                      const void* __restrict__ kp)
{
    const int* t32 = (const int*)tri;
    bool is64 = true;
    #pragma unroll
    for (int i = 1; i < 32; i += 2) is64 = is64 && (t32[i] == 0);

    int gid = blockIdx.x * blockDim.x + threadIdx.x;
    int stride = gridDim.x * blockDim.x;
    if (is64) {
        const long long* a = (const long long*)tri;
        for (int i = gid; i < NF_ * 3; i += stride) g_tri[i] = (int)a[i];
        const long long* b = (const long long*)pbuf;
        for (int i = gid; i < NV_ * 8; i += stride) g_pbuf[i] = (int)b[i];
        const long long* c = (const long long*)kp;
        for (int i = gid; i < NK_; i += stride) g_kp[i] = (int)c[i];
    } else {
        const int* a = (const int*)tri;
        for (int i = gid; i < NF_ * 3; i += stride) g_tri[i] = a[i];
        const int* b = (const int*)pbuf;
        for (int i = gid; i < NV_ * 8; i += stride) g_pbuf[i] = b[i];
        const int* c = (const int*)kp;
        for (int i = gid; i < NK_; i += stride) g_kp[i] = c[i];
    }
}

// ============================================================
__global__ void k_prep(const float* __restrict__ coeff,
                       const float* __restrict__ meanshape)
{
    __shared__ float rx[256], ry[256], rz[256];
    int t = threadIdx.x;
    float s0 = 0.f, s1 = 0.f, s2 = 0.f;
    for (int v = t; v < NV_; v += 256) {
        s0 += meanshape[v * 3 + 0];
        s1 += meanshape[v * 3 + 1];
        s2 += meanshape[v * 3 + 2];
    }
    rx[t] = s0; ry[t] = s1; rz[t] = s2;
    __syncthreads();
    for (int off = 128; off > 0; off >>= 1) {
        if (t < off) { rx[t] += rx[t + off]; ry[t] += ry[t + off]; rz[t] += rz[t + off]; }
        __syncthreads();
    }
    if (t == 0) {
        g_mean[0] = rx[0] / (float)NV_;
        g_mean[1] = ry[0] / (float)NV_;
        g_mean[2] = rz[0] / (float)NV_;
    }
    float ax = coeff[t * CST + 224], ay = coeff[t * CST + 225], az = coeff[t * CST + 226];
    float sx = sinf(ax), cx = cosf(ax);
    float sy = sinf(ay), cy = cosf(ay);
    float sz = sinf(az), cz = cosf(az);
    float* M = g_rot + t * 9;
    M[0] = cz * cy;  M[1] = cz * sy * sx - sz * cx;  M[2] = cz * sy * cx + sz * sx;
    M[3] = sz * cy;  M[4] = sz * sy * sx + cz * cx;  M[5] = sz * sy * cx - cz * sx;
    M[6] = -sy;      M[7] = cy * sx;                 M[8] = cy * cx;
}

// ============================================================
__global__ void k_coeffB(const float* __restrict__ coeff)
{
    int b = blockIdx.x, c = threadIdx.x;  // c: 0..111
    float x = coeff[b * CST + 2 * c];
    float y = coeff[b * CST + 2 * c + 1];
    uint32_t hi, lo;
    split2(x, y, hi, lo);
    int w = c & 7;
    int pos = (c & ~7) + ((w & 3) * 2 + (w >> 2));
    g_Bpk[b * 112 + pos] = make_uint2(hi, lo);
}

// ============================================================
// k_hmma: shape GEMM only (K=144), warp tile m32 x n64,
// block 64 rows x 256 batches (round-9 config).
// ============================================================
__global__ __launch_bounds__(256, 2) void k_hmma(
    const float* __restrict__ idBase, const float* __restrict__ exBase,
    const float* __restrict__ meanshape)
{
    int t = threadIdx.x;
    int w = t >> 5, lane = t & 31;
    int g = lane >> 2, tig = lane & 3;
    int wm = w & 1, wn = w >> 1;
    int r0 = blockIdx.x * 64;

    int rw0 = r0 + wm * 32 + g;
    int rows[4] = {rw0, rw0 + 8, rw0 + 16, rw0 + 24};
    size_t lrows[4];
    #pragma unroll
    for (int s = 0; s < 4; ++s)
        lrows[s] = (size_t)(rows[s] < NR_ ? rows[s] : NR_ - 1);
    int n0 = wn * 64;

    float acc[8][8];
    #pragma unroll
    for (int j = 0; j < 8; ++j)
        #pragma unroll
        for (int q = 0; q < 8; ++q) acc[j][q] = 0.f;

    for (int c = 0; c < 9; ++c) {
        int kw = c * 8;
        const float* ab;
        int kd, poff;
        if (c < 5) { ab = idBase; kd = 80; poff = 0; }
        else       { ab = exBase; kd = 64; poff = 40; }
        int p0 = kw + tig - poff;
        uint2 a00 = load_split(ab, kd, lrows[0], p0);
        uint2 a01 = load_split(ab, kd, lrows[1], p0);
        uint2 a02 = load_split(ab, kd, lrows[0], p0 + 4);
        uint2 a03 = load_split(ab, kd, lrows[1], p0 + 4);
        uint2 a10 = load_split(ab, kd, lrows[2], p0);
        uint2 a11 = load_split(ab, kd, lrows[3], p0);
        uint2 a12 = load_split(ab, kd, lrows[2], p0 + 4);
        uint2 a13 = load_split(ab, kd, lrows[3], p0 + 4);

        const uint2* bbase = g_Bpk + (size_t)(n0 + g) * 112 + kw + 2 * tig;
        #pragma unroll
        for (int j = 0; j < 8; ++j) {
            uint4 bv = *reinterpret_cast<const uint4*>(bbase + (size_t)j * 8 * 112);
            mma_bf16(&acc[j][0], a00.x, a01.x, a02.x, a03.x, bv.x, bv.z);
            mma_bf16(&acc[j][0], a00.x, a01.x, a02.x, a03.x, bv.y, bv.w);
            mma_bf16(&acc[j][0], a00.y, a01.y, a02.y, a03.y, bv.x, bv.z);
            mma_bf16(&acc[j][4], a10.x, a11.x, a12.x, a13.x, bv.x, bv.z);
            mma_bf16(&acc[j][4], a10.x, a11.x, a12.x, a13.x, bv.y, bv.w);
            mma_bf16(&acc[j][4], a10.y, a11.y, a12.y, a13.y, bv.x, bv.z);
        }
    }

    float addv[4];
    #pragma unroll
    for (int s = 0; s < 4; ++s)
        addv[s] = (rows[s] < NR_) ? meanshape[rows[s]] - g_mean[rows[s] % 3] : 0.f;
    #pragma unroll
    for (int j = 0; j < 8; ++j) {
        int col = n0 + j * 8 + 2 * tig;
        #pragma unroll
        for (int s = 0; s < 4; ++s) {
            if (rows[s] < NR_) {
                int base = (s >> 1) * 4 + (s & 1) * 2;
                *reinterpret_cast<float2*>(g_face_shape + (size_t)rows[s] * B_ + col) =
                    make_float2(acc[j][base] + addv[s], acc[j][base + 1] + addv[s]);
            }
        }
    }
}

// ============================================================
// tex_tile_small: texture GEMM (K=80), warp tile m16 x n64,
// block 32 rows x 256 batches — low register footprint (~70)
// so it can be mixed into the gather kernel without hurting occupancy.
// ============================================================
__device__ __forceinline__ void tex_tile_small(
    int tile, const float* __restrict__ texBase,
    const float* __restrict__ meantex)
{
    int t = threadIdx.x;
    int w = t >> 5, lane = t & 31;
    int g = lane >> 2, tig = lane & 3;
    int wm = w & 1, wn = w >> 1;
    int r0 = tile * 32;

    int row0 = r0 + wm * 16 + g;
    int row1 = row0 + 8;
    size_t lrow0 = (size_t)(row0 < NR_ ? row0 : NR_ - 1);
    size_t lrow1 = (size_t)(row1 < NR_ ? row1 : NR_ - 1);
    int n0 = wn * 64;

    float acc[8][4];
    #pragma unroll
    for (int j = 0; j < 8; ++j)
        #pragma unroll
        for (int q = 0; q < 4; ++q) acc[j][q] = 0.f;

    for (int c = 0; c < 5; ++c) {
        int kw = c * 8;
        int p0 = kw + tig;
        uint2 a0 = load_split(texBase, 80, lrow0, p0);
        uint2 a1 = load_split(texBase, 80, lrow1, p0);
        uint2 a2 = load_split(texBase, 80, lrow0, p0 + 4);
        uint2 a3 = load_split(texBase, 80, lrow1, p0 + 4);

        const uint2* bbase = g_Bpk + (size_t)(n0 + g) * 112 + 72 + kw + 2 * tig;
        #pragma unroll
        for (int j = 0; j < 8; ++j) {
            uint4 bv = *reinterpret_cast<const uint4*>(bbase + (size_t)j * 8 * 112);
            mma_bf16(acc[j], a0.x, a1.x, a2.x, a3.x, bv.x, bv.z);
            mma_bf16(acc[j], a0.x, a1.x, a2.x, a3.x, bv.y, bv.w);
            mma_bf16(acc[j], a0.y, a1.y, a2.y, a3.y, bv.x, bv.z);
        }
    }

    float add0 = (row0 < NR_) ? meantex[row0] : 0.f;
    float add1 = (row1 < NR_) ? meantex[row1] : 0.f;
    #pragma unroll
    for (int j = 0; j < 8; ++j) {
        int col = n0 + j * 8 + 2 * tig;
        if (row0 < NR_)
            *reinterpret_cast<float2*>(g_tex + (size_t)row0 * B_ + col) =
                make_float2(acc[j][0] + add0, acc[j][1] + add0);
        if (row1 < NR_)
            *reinterpret_cast<float2*>(g_tex + (size_t)row1 * B_ + col) =
                make_float2(acc[j][2] + add1, acc[j][3] + add1);
    }
}

// ============================================================
// gather-phase device blocks (identical to round-9 passing kernel)
// ============================================================
__device__ __forceinline__ void proj_block(
    int bx, const float* __restrict__ coeff, float* __restrict__ dout, float* sm)
{
    float* s    = sm;          // [96][33]
    float* srot = sm + 3200;   // [32][12]
    int t = threadIdx.x;
    int g = bx % 8;
    int v0 = (bx / 8) * 32;
    int r0 = v0 * 3;

    for (int idx = t; idx < 32 * 12; idx += 256) {
        int b_l = idx / 12, k = idx % 12;
        int b = g * 32 + b_l;
        srot[b_l * 12 + k] = (k < 9) ? g_rot[b * 9 + k] : coeff[b * CST + 254 + (k - 9)];
    }
    #pragma unroll
    for (int it = 0; it < 12; it++) {
        int idx = t + it * 256;
        int row = idx >> 5, b_l = idx & 31;
        s[row * 33 + b_l] = (r0 + row < NR_) ?
            g_face_shape[(size_t)(r0 + row) * B_ + g * 32 + b_l] : 0.f;
    }
    __syncthreads();

    int b_l = t >> 3, j = t & 7;
    int b = g * 32 + b_l;
    float m0 = srot[b_l * 12 + 0], m1 = srot[b_l * 12 + 1], m2 = srot[b_l * 12 + 2];
    float m3 = srot[b_l * 12 + 3], m4 = srot[b_l * 12 + 4], m5 = srot[b_l * 12 + 5];
    float m6 = srot[b_l * 12 + 6], m7 = srot[b_l * 12 + 7], m8 = srot[b_l * 12 + 8];
    float tx = srot[b_l * 12 + 9], ty = srot[b_l * 12 + 10], tz = srot[b_l * 12 + 11];
    #pragma unroll
    for (int w = 0; w < 4; w++) {
        int v_l = j * 4 + w;
        int v = v0 + v_l;
        if (v < NV_) {
            float x = s[(v_l * 3 + 0) * 33 + b_l];
            float y = s[(v_l * 3 + 1) * 33 + b_l];
            float z = s[(v_l * 3 + 2) * 33 + b_l];
            float* o = dout + (size_t)b * NR_ + (size_t)v * 3;
            o[0] = fmaf(m0, x, fmaf(m1, y, fmaf(m2, z, tx)));
            o[1] = fmaf(m3, x, fmaf(m4, y, fmaf(m5, z, ty)));
            o[2] = fmaf(m6, x, fmaf(m7, y, fmaf(m8, z, tz)));
        }
    }
}

__device__ __forceinline__ void fn_block(int bx, int g)
{
    int t = threadIdx.x;
    int quad = bx * 8 + (t >> 5);
    int b = g * 32 + (t & 31);
    #pragma unroll
    for (int u = 0; u < 4; u++) {
        int fid = quad * 4 + u;
        if (fid > NF_) continue;
        float* fn = g_face_norm + (size_t)(fid * 3) * B_ + b;
        if (fid == NF_) {
            fn[0] = 0.f; fn[B_] = 0.f; fn[2 * B_] = 0.f;
            continue;
        }
        int i0 = g_tri[fid * 3 + 0], i1 = g_tri[fid * 3 + 1], i2 = g_tri[fid * 3 + 2];
        const float* fs = g_face_shape;
        size_t o0 = (size_t)(3 * i0) * B_ + b;
        size_t o1 = (size_t)(3 * i1) * B_ + b;
        size_t o2 = (size_t)(3 * i2) * B_ + b;
        float v1x = fs[o0], v1y = fs[o0 + B_], v1z = fs[o0 + 2 * B_];
        float v2x = fs[o1], v2y = fs[o1 + B_], v2z = fs[o1 + 2 * B_];
        float v3x = fs[o2], v3y = fs[o2 + B_], v3z = fs[o2 + 2 * B_];
        float e1x = v1x - v2x, e1y = v1y - v2y, e1z = v1z - v2z;
        float e2x = v2x - v3x, e2y = v2y - v3y, e2z = v2z - v3z;
        fn[0]      = e1y * e2z - e1z * e2y;
        fn[B_]     = e1z * e2x - e1x * e2z;
        fn[2 * B_] = e1x * e2y - e1y * e2x;
    }
}

__device__ __forceinline__ void color_block(
    int bx, int g, const float* __restrict__ coeff,
    float* __restrict__ dout, float* sm)
{
    const float A0C0   = 0.88622692545275801f;
    const float A1C1   = 1.77245385090551603f;
    const float A2C2   = 2.42703222385900050f;
    const float A2C2D0 = 0.70062326950125306f;
    const float A2C2H  = 1.21351611192950025f;

    float* sc = sm;          // [96][33]
    float* sg = sm + 3200;   // [32][27]
    int t = threadIdx.x;
    int v0 = bx * 32;

    for (int idx = t; idx < 32 * 27; idx += 256) {
        int b_l = idx / 27, kk = idx % 27;
        int k = kk / 3, c = kk % 3;
        float gv = coeff[(size_t)(g * 32 + b_l) * CST + 227 + c * 9 + k];
        if (k == 0) gv += 0.8f;
        sg[b_l * 27 + k * 3 + c] = gv;
    }
    __syncthreads();

    int vslot = t >> 5, b_l = t & 31;
    int b = g * 32 + b_l;
    #pragma unroll
    for (int it = 0; it < 4; it++) {
        int v_l = vslot + it * 8;
        int v = v0 + v_l;
        if (v < NV_) {
            const int4* pb4 = reinterpret_cast<const int4*>(g_pbuf + v * 8);
            int4 pa = pb4[0], pbv = pb4[1];
            int f[8] = {pa.x, pa.y, pa.z, pa.w, pbv.x, pbv.y, pbv.z, pbv.w};
            float sx = 0.f, sy = 0.f, sz = 0.f;
            #pragma unroll
            for (int i = 0; i < 8; i++) {
                const float* fn = g_face_norm + (size_t)(f[i] * 3) * B_ + b;
                sx += fn[0]; sy += fn[B_]; sz += fn[2 * B_];
            }
            float inv = rsqrtf(sx * sx + sy * sy + sz * sz);
            float nx = sx * inv, ny = sy * inv, nz = sz * inv;

            float Y[9];
            Y[0] = A0C0;
            Y[1] = -A1C1 * ny;
            Y[2] =  A1C1 * nz;
            Y[3] = -A1C1 * nx;
            Y[4] =  A2C2 * nx * ny;
            Y[5] = -A2C2 * ny * nz;
            Y[6] =  A2C2D0 * (3.f * nz * nz - 1.f);
            Y[7] = -A2C2 * nx * nz;
            Y[8] =  A2C2H * (nx * nx - ny * ny);

            const float* tx = g_tex + (size_t)(v * 3) * B_ + b;
            #pragma unroll
            for (int c = 0; c < 3; c++) {
                float l = 0.f;
                #pragma unroll
                for (int k = 0; k < 9; k++) l = fmaf(Y[k], sg[b_l * 27 + k * 3 + c], l);
                float col = tx[(size_t)c * B_] * l * (1.f / 255.f);
                sc[(v_l * 3 + c) * 33 + b_l] = fminf(fmaxf(col, 0.f), 1.f);
            }
        }
    }
    __syncthreads();

    int b_l2 = t >> 3, j = t & 7;
    int b2 = g * 32 + b_l2;
    #pragma unroll
    for (int w = 0; w < 4; w++) {
        int v_l = j * 4 + w;
        int v = v0 + v_l;
        if (v < NV_) {
            float* o = dout + OUT_COLOR + (size_t)b2 * NR_ + (size_t)v * 3;
            o[0] = sc[(v_l * 3 + 0) * 33 + b_l2];
            o[1] = sc[(v_l * 3 + 1) * 33 + b_l2];
            o[2] = sc[(v_l * 3 + 2) * 33 + b_l2];
        }
    }
}

// ============================================================
// k_mix1: tex small-tile gemm + proj blocks + fn(group 0) blocks
// ============================================================
__global__ __launch_bounds__(256, 3) void k_mix1(
    const float* __restrict__ texBase, const float* __restrict__ meantex,
    const float* __restrict__ coeff, float* __restrict__ dout)
{
    __shared__ __align__(16) float sm[3584];
    int bx = blockIdx.x;
    if (bx < NT32) {
        tex_tile_small(bx, texBase, meantex);
    } else if (bx < NT32 + NPROJ) {
        proj_block(bx - NT32, coeff, dout, sm);
    } else {
        fn_block(bx - NT32 - NPROJ, 0);
    }
}

// k_stage(g): color(g) + fn(g+1)
__global__ void k_stage(int g, const float* __restrict__ coeff,
                        float* __restrict__ dout)
{
    __shared__ __align__(16) float sm[4096];
    int bx = blockIdx.x;
    if (bx < NCOL) {
        color_block(bx, g, coeff, dout, sm);
    } else {
        fn_block(bx - NCOL, g + 1);
    }
}

// ============================================================
__global__ void k_tail(float* __restrict__ dout)
{
    int i = blockIdx.x * 256 + threadIdx.x;
    const int LM_N = B_ * NK_ * 3;
    if (i < LM_N) {
        int d = i % 3, r = i / 3;
        int k = r % NK_, b = r / NK_;
        int v = g_kp[k];
        dout[OUT_LM + i] = dout[(size_t)b * NR_ + (size_t)v * 3 + d];
    } else {
        int q = i - LM_N;
        if (q < NF_ * 3) dout[OUT_TRI + q] = (float)g_tri[q];
    }
}

// ============================================================
extern "C" void kernel_launch(void* const* d_in, const int* in_sizes, int n_in,
                              void* d_out, int out_size)
{
    (void)in_sizes; (void)n_in; (void)out_size;
    const float* coeff     = (const float*)d_in[0];
    const float* meanshape = (const float*)d_in[1];
    const float* idBase    = (const float*)d_in[2];
    const float* exBase    = (const float*)d_in[3];
    const float* meantex   = (const float*)d_in[4];
    const float* texBase   = (const float*)d_in[5];
    const void*  tri       = d_in[6];
    const void*  pbuf      = d_in[7];
    const void*  kp        = d_in[8];
    float* dout = (float*)d_out;

    k_idx    <<<128, 256>>>(tri, pbuf, kp);
    k_prep   <<<1, 256>>>(coeff, meanshape);
    k_coeffB <<<256, 112>>>(coeff);
    k_hmma   <<<NT64, 256>>>(idBase, exBase, meanshape);
    k_mix1   <<<NT32 + NPROJ + NFN, 256>>>(texBase, meantex, coeff, dout);
    for (int g = 0; g < 7; g++)
        k_stage<<<NCOL + NFN, 256>>>(g, coeff, dout);
    k_stage<<<NCOL, 256>>>(7, coeff, dout);
    k_tail<<<(B_ * NK_ * 3 + NF_ * 3 + 255) / 256, 256>>>(dout);
}

// round 14
// speedup vs baseline: 1.1269x; 1.1232x over previous
#include <cuda_runtime.h>
#include <cuda_bf16.h>
#include <math.h>
#include <stdint.h>

#define B_  256
#define NV_ 35709
#define NR_ 107127          // NV*3
#define NF_ 70789
#define NK_ 68
#define CST 257

#define OUT_COLOR ((size_t)B_ * NR_)
#define OUT_LM    ((size_t)2 * B_ * NR_)
#define OUT_TRI   (OUT_LM + (size_t)B_ * NK_ * 3)

#define NPROJ (((NV_ + 31) / 32) * 8)    // 8928 proj blocks
#define NFN   ((NF_ + 1 + 31) / 32)      // 2213 fn blocks per group (32 faces/block)
#define NCOL  ((NV_ + 31) / 32)          // 1116 color blocks per group
#define NT64  ((NR_ + 63) / 64)          // 1674 gemm row tiles
#define NTAIL ((B_ * NK_ * 3 + NF_ * 3 + 255) / 256)

// -------- device scratch --------
__device__ float g_mean[3];
__device__ float g_rot[B_ * 9];
__device__ uint2 g_Bpk[B_ * 112];                          // coeff hi/lo (chunk-permuted)
__device__ float g_face_shape[(size_t)NR_ * B_];           // [row][b]
__device__ float g_tex[(size_t)NR_ * B_];                  // [row][b]
__device__ float g_face_norm[(size_t)(NF_ + 1) * 3 * B_];  // [face*3+d][b]
__device__ int   g_tri[NF_ * 3];
__device__ int   g_pbuf[NV_ * 8];
__device__ int   g_kp[NK_];

// bf16 hi/lo split of a float pair: hi = rn(a),rn(b); lo = rn(residual)
__device__ __forceinline__ void split2(float a, float b, uint32_t& hi, uint32_t& lo) {
    __nv_bfloat16 ah = __float2bfloat16_rn(a), bh = __float2bfloat16_rn(b);
    float ar = a - __bfloat162float(ah), br = b - __bfloat162float(bh);
    __nv_bfloat162 h = __halves2bfloat162(ah, bh);
    __nv_bfloat162 l = __halves2bfloat162(__float2bfloat16_rn(ar), __float2bfloat16_rn(br));
    hi = *reinterpret_cast<uint32_t*>(&h);
    lo = *reinterpret_cast<uint32_t*>(&l);
}

__device__ __forceinline__ uint2 load_split(const float* __restrict__ base,
                                            int kd, size_t row, int pair) {
    float2 v = *reinterpret_cast<const float2*>(base + row * kd + 2 * pair);
    uint32_t hi, lo;
    split2(v.x, v.y, hi, lo);
    return make_uint2(hi, lo);
}

__device__ __forceinline__ void mma_bf16(float* c,
    uint32_t a0, uint32_t a1, uint32_t a2, uint32_t a3,
    uint32_t b0, uint32_t b1)
{
    asm volatile(
        "mma.sync.aligned.m16n8k16.row.col.f32.bf16.bf16.f32 "
        "{%0,%1,%2,%3}, {%4,%5,%6,%7}, {%8,%9}, {%0,%1,%2,%3};"
        : "+f"(c[0]), "+f"(c[1]), "+f"(c[2]), "+f"(c[3])
        : "r"(a0), "r"(a1), "r"(a2), "r"(a3), "r"(b0), "r"(b1));
}

// ============================================================
// k_pre: fused idx-convert + prep + coeffB pack (block-ranged)
// blocks [0,128): idx, [128]: prep, [129,257): coeffB (2 batches/block)
// ============================================================
__device__ __forceinline__ void idx_blocks(
    int bx, const void* __restrict__ tri,
    const void* __restrict__ pbuf, const void* __restrict__ kp)
{
    const int* t32 = (const int*)tri;
    bool is64 = true;
    #pragma unroll
    for (int i = 1; i < 32; i += 2) is64 = is64 && (t32[i] == 0);

    int gid = bx * 256 + threadIdx.x;
    int stride = 128 * 256;
    if (is64) {
        const long long* a = (const long long*)tri;
        for (int i = gid; i < NF_ * 3; i += stride) g_tri[i] = (int)a[i];
        const long long* b = (const long long*)pbuf;
        for (int i = gid; i < NV_ * 8; i += stride) g_pbuf[i] = (int)b[i];
        const long long* c = (const long long*)kp;
        for (int i = gid; i < NK_; i += stride) g_kp[i] = (int)c[i];
    } else {
        const int* a = (const int*)tri;
        for (int i = gid; i < NF_ * 3; i += stride) g_tri[i] = a[i];
        const int* b = (const int*)pbuf;
        for (int i = gid; i < NV_ * 8; i += stride) g_pbuf[i] = b[i];
        const int* c = (const int*)kp;
        for (int i = gid; i < NK_; i += stride) g_kp[i] = c[i];
    }
}

__device__ __forceinline__ void prep_block(
    const float* __restrict__ coeff, const float* __restrict__ meanshape,
    float* sm)
{
    float* rx = sm, *ry = sm + 256, *rz = sm + 512;
    int t = threadIdx.x;
    float s0 = 0.f, s1 = 0.f, s2 = 0.f;
    for (int v = t; v < NV_; v += 256) {
        s0 += meanshape[v * 3 + 0];
        s1 += meanshape[v * 3 + 1];
        s2 += meanshape[v * 3 + 2];
    }
    rx[t] = s0; ry[t] = s1; rz[t] = s2;
    __syncthreads();
    for (int off = 128; off > 0; off >>= 1) {
        if (t < off) { rx[t] += rx[t + off]; ry[t] += ry[t + off]; rz[t] += rz[t + off]; }
        __syncthreads();
    }
    if (t == 0) {
        g_mean[0] = rx[0] / (float)NV_;
        g_mean[1] = ry[0] / (float)NV_;
        g_mean[2] = rz[0] / (float)NV_;
    }
    float ax = coeff[t * CST + 224], ay = coeff[t * CST + 225], az = coeff[t * CST + 226];
    float sx = sinf(ax), cx = cosf(ax);
    float sy = sinf(ay), cy = cosf(ay);
    float sz = sinf(az), cz = cosf(az);
    float* M = g_rot + t * 9;
    M[0] = cz * cy;  M[1] = cz * sy * sx - sz * cx;  M[2] = cz * sy * cx + sz * sx;
    M[3] = sz * cy;  M[4] = sz * sy * sx + cz * cx;  M[5] = sz * sy * cx - cz * sx;
    M[6] = -sy;      M[7] = cy * sx;                 M[8] = cy * cx;
}

__device__ __forceinline__ void coeffB_block(int bx, const float* __restrict__ coeff)
{
    int t = threadIdx.x;
    if (t >= 224) return;
    int b = bx * 2 + t / 112;
    int c = t % 112;
    float x = coeff[b * CST + 2 * c];
    float y = coeff[b * CST + 2 * c + 1];
    uint32_t hi, lo;
    split2(x, y, hi, lo);
    int w = c & 7;
    int pos = (c & ~7) + ((w & 3) * 2 + (w >> 2));
    g_Bpk[b * 112 + pos] = make_uint2(hi, lo);
}

__global__ void k_pre(const void* __restrict__ tri,
                      const void* __restrict__ pbuf,
                      const void* __restrict__ kp,
                      const float* __restrict__ coeff,
                      const float* __restrict__ meanshape)
{
    __shared__ float sm[768];
    int bx = blockIdx.x;
    if (bx < 128) {
        idx_blocks(bx, tri, pbuf, kp);
    } else if (bx == 128) {
        prep_block(coeff, meanshape, sm);
    } else {
        coeffB_block(bx - 129, coeff);
    }
}

// ============================================================
// k_hmma: bf16-split tensor-core GEMM (round-9 config, unchanged).
// blockIdx.x < NT64: face_shape (K=144); else face_texture (K=80).
// Warp tile m32 x n64; block 64 rows x 256 batches.
// ============================================================
__global__ __launch_bounds__(256, 2) void k_hmma(
    const float* __restrict__ idBase, const float* __restrict__ exBase,
    const float* __restrict__ texBase,
    const float* __restrict__ meanshape, const float* __restrict__ meantex)
{
    int t = threadIdx.x;
    int w = t >> 5, lane = t & 31;
    int g = lane >> 2, tig = lane & 3;
    int wm = w & 1, wn = w >> 1;
    bool is_shape = (blockIdx.x < NT64);
    int tile = is_shape ? blockIdx.x : (blockIdx.x - NT64);
    int r0 = tile * 64;
    int nch = is_shape ? 9 : 5;
    int kboff = is_shape ? 0 : 72;

    int rw0 = r0 + wm * 32 + g;
    int rows[4] = {rw0, rw0 + 8, rw0 + 16, rw0 + 24};
    size_t lrows[4];
    #pragma unroll
    for (int s = 0; s < 4; ++s)
        lrows[s] = (size_t)(rows[s] < NR_ ? rows[s] : NR_ - 1);
    int n0 = wn * 64;

    float acc[8][8];
    #pragma unroll
    for (int j = 0; j < 8; ++j)
        #pragma unroll
        for (int q = 0; q < 8; ++q) acc[j][q] = 0.f;

    for (int c = 0; c < nch; ++c) {
        int kw = c * 8;
        const float* ab;
        int kd, poff;
        if (is_shape) {
            if (c < 5) { ab = idBase; kd = 80; poff = 0; }
            else       { ab = exBase; kd = 64; poff = 40; }
        } else       { ab = texBase; kd = 80; poff = 0; }
        int p0 = kw + tig - poff;
        uint2 a00 = load_split(ab, kd, lrows[0], p0);
        uint2 a01 = load_split(ab, kd, lrows[1], p0);
        uint2 a02 = load_split(ab, kd, lrows[0], p0 + 4);
        uint2 a03 = load_split(ab, kd, lrows[1], p0 + 4);
        uint2 a10 = load_split(ab, kd, lrows[2], p0);
        uint2 a11 = load_split(ab, kd, lrows[3], p0);
        uint2 a12 = load_split(ab, kd, lrows[2], p0 + 4);
        uint2 a13 = load_split(ab, kd, lrows[3], p0 + 4);

        const uint2* bbase = g_Bpk + (size_t)(n0 + g) * 112 + kboff + kw + 2 * tig;
        #pragma unroll
        for (int j = 0; j < 8; ++j) {
            uint4 bv = *reinterpret_cast<const uint4*>(bbase + (size_t)j * 8 * 112);
            mma_bf16(&acc[j][0], a00.x, a01.x, a02.x, a03.x, bv.x, bv.z);
            mma_bf16(&acc[j][0], a00.x, a01.x, a02.x, a03.x, bv.y, bv.w);
            mma_bf16(&acc[j][0], a00.y, a01.y, a02.y, a03.y, bv.x, bv.z);
            mma_bf16(&acc[j][4], a10.x, a11.x, a12.x, a13.x, bv.x, bv.z);
            mma_bf16(&acc[j][4], a10.x, a11.x, a12.x, a13.x, bv.y, bv.w);
            mma_bf16(&acc[j][4], a10.y, a11.y, a12.y, a13.y, bv.x, bv.z);
        }
    }

    float addv[4];
    float* dst;
    if (is_shape) {
        #pragma unroll
        for (int s = 0; s < 4; ++s)
            addv[s] = (rows[s] < NR_) ? meanshape[rows[s]] - g_mean[rows[s] % 3] : 0.f;
        dst = g_face_shape;
    } else {
        #pragma unroll
        for (int s = 0; s < 4; ++s)
            addv[s] = (rows[s] < NR_) ? meantex[rows[s]] : 0.f;
        dst = g_tex;
    }
    #pragma unroll
    for (int j = 0; j < 8; ++j) {
        int col = n0 + j * 8 + 2 * tig;
        #pragma unroll
        for (int s = 0; s < 4; ++s) {
            if (rows[s] < NR_) {
                int base = (s >> 1) * 4 + (s & 1) * 2;
                *reinterpret_cast<float2*>(dst + (size_t)rows[s] * B_ + col) =
                    make_float2(acc[j][base] + addv[s], acc[j][base + 1] + addv[s]);
            }
        }
    }
}

// ============================================================
// gather-phase device blocks (byte-identical to round-9 champion)
// ============================================================
__device__ __forceinline__ void proj_block(
    int bx, const float* __restrict__ coeff, float* __restrict__ dout, float* sm)
{
    float* s    = sm;          // [96][33]
    float* srot = sm + 3200;   // [32][12]
    int t = threadIdx.x;
    int g = bx % 8;
    int v0 = (bx / 8) * 32;
    int r0 = v0 * 3;

    for (int idx = t; idx < 32 * 12; idx += 256) {
        int b_l = idx / 12, k = idx % 12;
        int b = g * 32 + b_l;
        srot[b_l * 12 + k] = (k < 9) ? g_rot[b * 9 + k] : coeff[b * CST + 254 + (k - 9)];
    }
    #pragma unroll
    for (int it = 0; it < 12; it++) {
        int idx = t + it * 256;
        int row = idx >> 5, b_l = idx & 31;
        s[row * 33 + b_l] = (r0 + row < NR_) ?
            g_face_shape[(size_t)(r0 + row) * B_ + g * 32 + b_l] : 0.f;
    }
    __syncthreads();

    int b_l = t >> 3, j = t & 7;
    int b = g * 32 + b_l;
    float m0 = srot[b_l * 12 + 0], m1 = srot[b_l * 12 + 1], m2 = srot[b_l * 12 + 2];
    float m3 = srot[b_l * 12 + 3], m4 = srot[b_l * 12 + 4], m5 = srot[b_l * 12 + 5];
    float m6 = srot[b_l * 12 + 6], m7 = srot[b_l * 12 + 7], m8 = srot[b_l * 12 + 8];
    float tx = srot[b_l * 12 + 9], ty = srot[b_l * 12 + 10], tz = srot[b_l * 12 + 11];
    #pragma unroll
    for (int w = 0; w < 4; w++) {
        int v_l = j * 4 + w;
        int v = v0 + v_l;
        if (v < NV_) {
            float x = s[(v_l * 3 + 0) * 33 + b_l];
            float y = s[(v_l * 3 + 1) * 33 + b_l];
            float z = s[(v_l * 3 + 2) * 33 + b_l];
            float* o = dout + (size_t)b * NR_ + (size_t)v * 3;
            o[0] = fmaf(m0, x, fmaf(m1, y, fmaf(m2, z, tx)));
            o[1] = fmaf(m3, x, fmaf(m4, y, fmaf(m5, z, ty)));
            o[2] = fmaf(m6, x, fmaf(m7, y, fmaf(m8, z, tz)));
        }
    }
}

__device__ __forceinline__ void fn_block(int bx, int g)
{
    int t = threadIdx.x;
    int quad = bx * 8 + (t >> 5);
    int b = g * 32 + (t & 31);
    #pragma unroll
    for (int u = 0; u < 4; u++) {
        int fid = quad * 4 + u;
        if (fid > NF_) continue;
        float* fn = g_face_norm + (size_t)(fid * 3) * B_ + b;
        if (fid == NF_) {
            fn[0] = 0.f; fn[B_] = 0.f; fn[2 * B_] = 0.f;
            continue;
        }
        int i0 = g_tri[fid * 3 + 0], i1 = g_tri[fid * 3 + 1], i2 = g_tri[fid * 3 + 2];
        const float* fs = g_face_shape;
        size_t o0 = (size_t)(3 * i0) * B_ + b;
        size_t o1 = (size_t)(3 * i1) * B_ + b;
        size_t o2 = (size_t)(3 * i2) * B_ + b;
        float v1x = fs[o0], v1y = fs[o0 + B_], v1z = fs[o0 + 2 * B_];
        float v2x = fs[o1], v2y = fs[o1 + B_], v2z = fs[o1 + 2 * B_];
        float v3x = fs[o2], v3y = fs[o2 + B_], v3z = fs[o2 + 2 * B_];
        float e1x = v1x - v2x, e1y = v1y - v2y, e1z = v1z - v2z;
        float e2x = v2x - v3x, e2y = v2y - v3y, e2z = v2z - v3z;
        fn[0]      = e1y * e2z - e1z * e2y;
        fn[B_]     = e1z * e2x - e1x * e2z;
        fn[2 * B_] = e1x * e2y - e1y * e2x;
    }
}

__device__ __forceinline__ void color_block(
    int bx, int g, const float* __restrict__ coeff,
    float* __restrict__ dout, float* sm)
{
    const float A0C0   = 0.88622692545275801f;
    const float A1C1   = 1.77245385090551603f;
    const float A2C2   = 2.42703222385900050f;
    const float A2C2D0 = 0.70062326950125306f;
    const float A2C2H  = 1.21351611192950025f;

    float* sc = sm;          // [96][33]
    float* sg = sm + 3200;   // [32][27]
    int t = threadIdx.x;
    int v0 = bx * 32;

    for (int idx = t; idx < 32 * 27; idx += 256) {
        int b_l = idx / 27, kk = idx % 27;
        int k = kk / 3, c = kk % 3;
        float gv = coeff[(size_t)(g * 32 + b_l) * CST + 227 + c * 9 + k];
        if (k == 0) gv += 0.8f;
        sg[b_l * 27 + k * 3 + c] = gv;
    }
    __syncthreads();

    int vslot = t >> 5, b_l = t & 31;
    int b = g * 32 + b_l;
    #pragma unroll
    for (int it = 0; it < 4; it++) {
        int v_l = vslot + it * 8;
        int v = v0 + v_l;
        if (v < NV_) {
            const int4* pb4 = reinterpret_cast<const int4*>(g_pbuf + v * 8);
            int4 pa = pb4[0], pbv = pb4[1];
            int f[8] = {pa.x, pa.y, pa.z, pa.w, pbv.x, pbv.y, pbv.z, pbv.w};
            float sx = 0.f, sy = 0.f, sz = 0.f;
            #pragma unroll
            for (int i = 0; i < 8; i++) {
                const float* fn = g_face_norm + (size_t)(f[i] * 3) * B_ + b;
                sx += fn[0]; sy += fn[B_]; sz += fn[2 * B_];
            }
            float inv = rsqrtf(sx * sx + sy * sy + sz * sz);
            float nx = sx * inv, ny = sy * inv, nz = sz * inv;

            float Y[9];
            Y[0] = A0C0;
            Y[1] = -A1C1 * ny;
            Y[2] =  A1C1 * nz;
            Y[3] = -A1C1 * nx;
            Y[4] =  A2C2 * nx * ny;
            Y[5] = -A2C2 * ny * nz;
            Y[6] =  A2C2D0 * (3.f * nz * nz - 1.f);
            Y[7] = -A2C2 * nx * nz;
            Y[8] =  A2C2H * (nx * nx - ny * ny);

            const float* tx = g_tex + (size_t)(v * 3) * B_ + b;
            #pragma unroll
            for (int c = 0; c < 3; c++) {
                float l = 0.f;
                #pragma unroll
                for (int k = 0; k < 9; k++) l = fmaf(Y[k], sg[b_l * 27 + k * 3 + c], l);
                float col = tx[(size_t)c * B_] * l * (1.f / 255.f);
                sc[(v_l * 3 + c) * 33 + b_l] = fminf(fmaxf(col, 0.f), 1.f);
            }
        }
    }
    __syncthreads();

    int b_l2 = t >> 3, j = t & 7;
    int b2 = g * 32 + b_l2;
    #pragma unroll
    for (int w = 0; w < 4; w++) {
        int v_l = j * 4 + w;
        int v = v0 + v_l;
        if (v < NV_) {
            float* o = dout + OUT_COLOR + (size_t)b2 * NR_ + (size_t)v * 3;
            o[0] = sc[(v_l * 3 + 0) * 33 + b_l2];
            o[1] = sc[(v_l * 3 + 1) * 33 + b_l2];
            o[2] = sc[(v_l * 3 + 2) * 33 + b_l2];
        }
    }
}

__device__ __forceinline__ void tail_block(int bx, float* __restrict__ dout)
{
    int i = bx * 256 + threadIdx.x;
    const int LM_N = B_ * NK_ * 3;
    if (i < LM_N) {
        int d = i % 3, r = i / 3;
        int k = r % NK_, b = r / NK_;
        int v = g_kp[k];
        dout[OUT_LM + i] = dout[(size_t)b * NR_ + (size_t)v * 3 + d];
    } else {
        int q = i - LM_N;
        if (q < NF_ * 3) dout[OUT_TRI + q] = (float)g_tri[q];
    }
}

// ============================================================
// k_mix1: proj blocks + fn(group 0) + fn(group 1)
// ============================================================
__global__ void k_mix1(const float* __restrict__ coeff, float* __restrict__ dout)
{
    __shared__ __align__(16) float sm[3584];
    int bx = blockIdx.x;
    if (bx < NPROJ) {
        proj_block(bx, coeff, dout, sm);
    } else if (bx < NPROJ + NFN) {
        fn_block(bx - NPROJ, 0);
    } else {
        fn_block(bx - NPROJ - NFN, 1);
    }
}

// k_stage(G): color(2G) + color(2G+1) + fn(2G+2) + fn(2G+3)
// (fn omitted on last stage; tail folded into stage 0)
__global__ void k_stage(int G, const float* __restrict__ coeff,
                        float* __restrict__ dout)
{
    __shared__ __align__(16) float sm[4096];
    int bx = blockIdx.x;
    if (bx < NCOL) {
        color_block(bx, 2 * G, coeff, dout, sm);
    } else if (bx < 2 * NCOL) {
        color_block(bx - NCOL, 2 * G + 1, coeff, dout, sm);
    } else if (bx < 2 * NCOL + NFN) {
        if (G < 3) fn_block(bx - 2 * NCOL, 2 * G + 2);
        else       tail_block(bx - 2 * NCOL, dout);
    } else if (bx < 2 * NCOL + 2 * NFN) {
        if (G < 3) fn_block(bx - 2 * NCOL - NFN, 2 * G + 3);
    }
}

// ============================================================
extern "C" void kernel_launch(void* const* d_in, const int* in_sizes, int n_in,
                              void* d_out, int out_size)
{
    (void)in_sizes; (void)n_in; (void)out_size;
    const float* coeff     = (const float*)d_in[0];
    const float* meanshape = (const float*)d_in[1];
    const float* idBase    = (const float*)d_in[2];
    const float* exBase    = (const float*)d_in[3];
    const float* meantex   = (const float*)d_in[4];
    const float* texBase   = (const float*)d_in[5];
    const void*  tri       = d_in[6];
    const void*  pbuf      = d_in[7];
    const void*  kp        = d_in[8];
    float* dout = (float*)d_out;

    k_pre  <<<257, 256>>>(tri, pbuf, kp, coeff, meanshape);
    k_hmma <<<2 * NT64, 256>>>(idBase, exBase, texBase, meanshape, meantex);
    k_mix1 <<<NPROJ + 2 * NFN, 256>>>(coeff, dout);
    for (int G = 0; G < 3; G++)
        k_stage<<<2 * NCOL + 2 * NFN, 256>>>(G, coeff, dout);
    // last stage: colors 6,7 + tail (no fn); tail blocks occupy the fn(2G+2) slot
    k_stage<<<2 * NCOL + ((NTAIL > NFN) ? NFN + NTAIL : NFN + NTAIL), 256>>>(3, coeff, dout);
}

// round 15
// speedup vs baseline: 1.1284x; 1.0013x over previous
#include <cuda_runtime.h>
#include <cuda_bf16.h>
#include <math.h>
#include <stdint.h>

#define B_  256
#define NV_ 35709
#define NR_ 107127          // NV*3
#define NF_ 70789
#define NK_ 68
#define CST 257

#define OUT_COLOR ((size_t)B_ * NR_)
#define OUT_LM    ((size_t)2 * B_ * NR_)
#define OUT_TRI   (OUT_LM + (size_t)B_ * NK_ * 3)

#define NPROJ (((NV_ + 31) / 32) * 8)    // 8928 proj blocks
#define NFN   ((NF_ + 1 + 31) / 32)      // 2213 fn blocks per group (32 faces/block)
#define NCOL  ((NV_ + 31) / 32)          // 1116 color blocks per group
#define NT64  ((NR_ + 63) / 64)          // 1674 gemm row tiles
#define NTAIL ((B_ * NK_ * 3 + NF_ * 3 + 255) / 256)

// -------- device scratch --------
__device__ float g_mean[3];
__device__ float g_rot[B_ * 9];
__device__ uint2 g_Bpk[B_ * 112];                          // coeff hi/lo (chunk-permuted)
__device__ float g_face_shape[(size_t)NR_ * B_];           // [row][b]
__device__ float g_tex[(size_t)NR_ * B_];                  // [row][b]
__device__ float g_face_norm[(size_t)(NF_ + 1) * 3 * B_];  // [face*3+d][b]
__device__ int   g_tri[NF_ * 3];
__device__ int   g_pbuf[NV_ * 8];
__device__ int   g_kp[NK_];

// bf16 hi/lo split of a float pair: hi = rn(a),rn(b); lo = rn(residual)
__device__ __forceinline__ void split2(float a, float b, uint32_t& hi, uint32_t& lo) {
    __nv_bfloat16 ah = __float2bfloat16_rn(a), bh = __float2bfloat16_rn(b);
    float ar = a - __bfloat162float(ah), br = b - __bfloat162float(bh);
    __nv_bfloat162 h = __halves2bfloat162(ah, bh);
    __nv_bfloat162 l = __halves2bfloat162(__float2bfloat16_rn(ar), __float2bfloat16_rn(br));
    hi = *reinterpret_cast<uint32_t*>(&h);
    lo = *reinterpret_cast<uint32_t*>(&l);
}

__device__ __forceinline__ uint2 load_split(const float* __restrict__ base,
                                            int kd, size_t row, int pair) {
    float2 v = *reinterpret_cast<const float2*>(base + row * kd + 2 * pair);
    uint32_t hi, lo;
    split2(v.x, v.y, hi, lo);
    return make_uint2(hi, lo);
}

__device__ __forceinline__ void mma_bf16(float* c,
    uint32_t a0, uint32_t a1, uint32_t a2, uint32_t a3,
    uint32_t b0, uint32_t b1)
{
    asm volatile(
        "mma.sync.aligned.m16n8k16.row.col.f32.bf16.bf16.f32 "
        "{%0,%1,%2,%3}, {%4,%5,%6,%7}, {%8,%9}, {%0,%1,%2,%3};"
        : "+f"(c[0]), "+f"(c[1]), "+f"(c[2]), "+f"(c[3])
        : "r"(a0), "r"(a1), "r"(a2), "r"(a3), "r"(b0), "r"(b1));
}

// ============================================================
// k_pre: fused idx-convert + prep + coeffB pack (block-ranged)
// ============================================================
__device__ __forceinline__ void idx_blocks(
    int bx, const void* __restrict__ tri,
    const void* __restrict__ pbuf, const void* __restrict__ kp)
{
    const int* t32 = (const int*)tri;
    bool is64 = true;
    #pragma unroll
    for (int i = 1; i < 32; i += 2) is64 = is64 && (t32[i] == 0);

    int gid = bx * 256 + threadIdx.x;
    int stride = 128 * 256;
    if (is64) {
        const long long* a = (const long long*)tri;
        for (int i = gid; i < NF_ * 3; i += stride) g_tri[i] = (int)a[i];
        const long long* b = (const long long*)pbuf;
        for (int i = gid; i < NV_ * 8; i += stride) g_pbuf[i] = (int)b[i];
        const long long* c = (const long long*)kp;
        for (int i = gid; i < NK_; i += stride) g_kp[i] = (int)c[i];
    } else {
        const int* a = (const int*)tri;
        for (int i = gid; i < NF_ * 3; i += stride) g_tri[i] = a[i];
        const int* b = (const int*)pbuf;
        for (int i = gid; i < NV_ * 8; i += stride) g_pbuf[i] = b[i];
        const int* c = (const int*)kp;
        for (int i = gid; i < NK_; i += stride) g_kp[i] = c[i];
    }
}

__device__ __forceinline__ void prep_block(
    const float* __restrict__ coeff, const float* __restrict__ meanshape,
    float* sm)
{
    float* rx = sm, *ry = sm + 256, *rz = sm + 512;
    int t = threadIdx.x;
    float s0 = 0.f, s1 = 0.f, s2 = 0.f;
    for (int v = t; v < NV_; v += 256) {
        s0 += meanshape[v * 3 + 0];
        s1 += meanshape[v * 3 + 1];
        s2 += meanshape[v * 3 + 2];
    }
    rx[t] = s0; ry[t] = s1; rz[t] = s2;
    __syncthreads();
    for (int off = 128; off > 0; off >>= 1) {
        if (t < off) { rx[t] += rx[t + off]; ry[t] += ry[t + off]; rz[t] += rz[t + off]; }
        __syncthreads();
    }
    if (t == 0) {
        g_mean[0] = rx[0] / (float)NV_;
        g_mean[1] = ry[0] / (float)NV_;
        g_mean[2] = rz[0] / (float)NV_;
    }
    float ax = coeff[t * CST + 224], ay = coeff[t * CST + 225], az = coeff[t * CST + 226];
    float sx = sinf(ax), cx = cosf(ax);
    float sy = sinf(ay), cy = cosf(ay);
    float sz = sinf(az), cz = cosf(az);
    float* M = g_rot + t * 9;
    M[0] = cz * cy;  M[1] = cz * sy * sx - sz * cx;  M[2] = cz * sy * cx + sz * sx;
    M[3] = sz * cy;  M[4] = sz * sy * sx + cz * cx;  M[5] = sz * sy * cx - cz * sx;
    M[6] = -sy;      M[7] = cy * sx;                 M[8] = cy * cx;
}

__device__ __forceinline__ void coeffB_block(int bx, const float* __restrict__ coeff)
{
    int t = threadIdx.x;
    if (t >= 224) return;
    int b = bx * 2 + t / 112;
    int c = t % 112;
    float x = coeff[b * CST + 2 * c];
    float y = coeff[b * CST + 2 * c + 1];
    uint32_t hi, lo;
    split2(x, y, hi, lo);
    int w = c & 7;
    int pos = (c & ~7) + ((w & 3) * 2 + (w >> 2));
    g_Bpk[b * 112 + pos] = make_uint2(hi, lo);
}

__global__ void k_pre(const void* __restrict__ tri,
                      const void* __restrict__ pbuf,
                      const void* __restrict__ kp,
                      const float* __restrict__ coeff,
                      const float* __restrict__ meanshape)
{
    __shared__ float sm[768];
    int bx = blockIdx.x;
    if (bx < 128) {
        idx_blocks(bx, tri, pbuf, kp);
    } else if (bx == 128) {
        prep_block(coeff, meanshape, sm);
    } else {
        coeffB_block(bx - 129, coeff);
    }
}

// ============================================================
// gemm_tile: bf16-split tensor-core GEMM tile (round-9 config).
// Warp tile m32 x n64; block 64 rows x 256 batches.
// ============================================================
__device__ __forceinline__ void gemm_tile(
    int tile, bool is_shape,
    const float* __restrict__ idBase, const float* __restrict__ exBase,
    const float* __restrict__ texBase,
    const float* __restrict__ meanshape, const float* __restrict__ meantex)
{
    int t = threadIdx.x;
    int w = t >> 5, lane = t & 31;
    int g = lane >> 2, tig = lane & 3;
    int wm = w & 1, wn = w >> 1;
    int r0 = tile * 64;
    int nch = is_shape ? 9 : 5;
    int kboff = is_shape ? 0 : 72;

    int rw0 = r0 + wm * 32 + g;
    int rows[4] = {rw0, rw0 + 8, rw0 + 16, rw0 + 24};
    size_t lrows[4];
    #pragma unroll
    for (int s = 0; s < 4; ++s)
        lrows[s] = (size_t)(rows[s] < NR_ ? rows[s] : NR_ - 1);
    int n0 = wn * 64;

    float acc[8][8];
    #pragma unroll
    for (int j = 0; j < 8; ++j)
        #pragma unroll
        for (int q = 0; q < 8; ++q) acc[j][q] = 0.f;

    for (int c = 0; c < nch; ++c) {
        int kw = c * 8;
        const float* ab;
        int kd, poff;
        if (is_shape) {
            if (c < 5) { ab = idBase; kd = 80; poff = 0; }
            else       { ab = exBase; kd = 64; poff = 40; }
        } else       { ab = texBase; kd = 80; poff = 0; }
        int p0 = kw + tig - poff;
        uint2 a00 = load_split(ab, kd, lrows[0], p0);
        uint2 a01 = load_split(ab, kd, lrows[1], p0);
        uint2 a02 = load_split(ab, kd, lrows[0], p0 + 4);
        uint2 a03 = load_split(ab, kd, lrows[1], p0 + 4);
        uint2 a10 = load_split(ab, kd, lrows[2], p0);
        uint2 a11 = load_split(ab, kd, lrows[3], p0);
        uint2 a12 = load_split(ab, kd, lrows[2], p0 + 4);
        uint2 a13 = load_split(ab, kd, lrows[3], p0 + 4);

        const uint2* bbase = g_Bpk + (size_t)(n0 + g) * 112 + kboff + kw + 2 * tig;
        #pragma unroll
        for (int j = 0; j < 8; ++j) {
            uint4 bv = *reinterpret_cast<const uint4*>(bbase + (size_t)j * 8 * 112);
            mma_bf16(&acc[j][0], a00.x, a01.x, a02.x, a03.x, bv.x, bv.z);
            mma_bf16(&acc[j][0], a00.x, a01.x, a02.x, a03.x, bv.y, bv.w);
            mma_bf16(&acc[j][0], a00.y, a01.y, a02.y, a03.y, bv.x, bv.z);
            mma_bf16(&acc[j][4], a10.x, a11.x, a12.x, a13.x, bv.x, bv.z);
            mma_bf16(&acc[j][4], a10.x, a11.x, a12.x, a13.x, bv.y, bv.w);
            mma_bf16(&acc[j][4], a10.y, a11.y, a12.y, a13.y, bv.x, bv.z);
        }
    }

    float addv[4];
    float* dst;
    if (is_shape) {
        #pragma unroll
        for (int s = 0; s < 4; ++s)
            addv[s] = (rows[s] < NR_) ? meanshape[rows[s]] - g_mean[rows[s] % 3] : 0.f;
        dst = g_face_shape;
    } else {
        #pragma unroll
        for (int s = 0; s < 4; ++s)
            addv[s] = (rows[s] < NR_) ? meantex[rows[s]] : 0.f;
        dst = g_tex;
    }
    #pragma unroll
    for (int j = 0; j < 8; ++j) {
        int col = n0 + j * 8 + 2 * tig;
        #pragma unroll
        for (int s = 0; s < 4; ++s) {
            if (rows[s] < NR_) {
                int base = (s >> 1) * 4 + (s & 1) * 2;
                *reinterpret_cast<float2*>(dst + (size_t)rows[s] * B_ + col) =
                    make_float2(acc[j][base] + addv[s], acc[j][base + 1] + addv[s]);
            }
        }
    }
}

__global__ __launch_bounds__(256, 2) void k_hmma_shape(
    const float* __restrict__ idBase, const float* __restrict__ exBase,
    const float* __restrict__ meanshape)
{
    gemm_tile(blockIdx.x, true, idBase, exBase, (const float*)0, meanshape, (const float*)0);
}

__global__ __launch_bounds__(256, 2) void k_hmma_tex(
    const float* __restrict__ texBase, const float* __restrict__ meantex)
{
    gemm_tile(blockIdx.x, false, (const float*)0, (const float*)0, texBase, (const float*)0, meantex);
}

// ============================================================
// gather-phase device blocks (byte-identical to R14 champion)
// ============================================================
__device__ __forceinline__ void proj_block(
    int bx, const float* __restrict__ coeff, float* __restrict__ dout, float* sm)
{
    float* s    = sm;          // [96][33]
    float* srot = sm + 3200;   // [32][12]
    int t = threadIdx.x;
    int g = bx % 8;
    int v0 = (bx / 8) * 32;
    int r0 = v0 * 3;

    for (int idx = t; idx < 32 * 12; idx += 256) {
        int b_l = idx / 12, k = idx % 12;
        int b = g * 32 + b_l;
        srot[b_l * 12 + k] = (k < 9) ? g_rot[b * 9 + k] : coeff[b * CST + 254 + (k - 9)];
    }
    #pragma unroll
    for (int it = 0; it < 12; it++) {
        int idx = t + it * 256;
        int row = idx >> 5, b_l = idx & 31;
        s[row * 33 + b_l] = (r0 + row < NR_) ?
            g_face_shape[(size_t)(r0 + row) * B_ + g * 32 + b_l] : 0.f;
    }
    __syncthreads();

    int b_l = t >> 3, j = t & 7;
    int b = g * 32 + b_l;
    float m0 = srot[b_l * 12 + 0], m1 = srot[b_l * 12 + 1], m2 = srot[b_l * 12 + 2];
    float m3 = srot[b_l * 12 + 3], m4 = srot[b_l * 12 + 4], m5 = srot[b_l * 12 + 5];
    float m6 = srot[b_l * 12 + 6], m7 = srot[b_l * 12 + 7], m8 = srot[b_l * 12 + 8];
    float tx = srot[b_l * 12 + 9], ty = srot[b_l * 12 + 10], tz = srot[b_l * 12 + 11];
    #pragma unroll
    for (int w = 0; w < 4; w++) {
        int v_l = j * 4 + w;
        int v = v0 + v_l;
        if (v < NV_) {
            float x = s[(v_l * 3 + 0) * 33 + b_l];
            float y = s[(v_l * 3 + 1) * 33 + b_l];
            float z = s[(v_l * 3 + 2) * 33 + b_l];
            float* o = dout + (size_t)b * NR_ + (size_t)v * 3;
            o[0] = fmaf(m0, x, fmaf(m1, y, fmaf(m2, z, tx)));
            o[1] = fmaf(m3, x, fmaf(m4, y, fmaf(m5, z, ty)));
            o[2] = fmaf(m6, x, fmaf(m7, y, fmaf(m8, z, tz)));
        }
    }
}

__device__ __forceinline__ void fn_block(int bx, int g)
{
    int t = threadIdx.x;
    int quad = bx * 8 + (t >> 5);
    int b = g * 32 + (t & 31);
    #pragma unroll
    for (int u = 0; u < 4; u++) {
        int fid = quad * 4 + u;
        if (fid > NF_) continue;
        float* fn = g_face_norm + (size_t)(fid * 3) * B_ + b;
        if (fid == NF_) {
            fn[0] = 0.f; fn[B_] = 0.f; fn[2 * B_] = 0.f;
            continue;
        }
        int i0 = g_tri[fid * 3 + 0], i1 = g_tri[fid * 3 + 1], i2 = g_tri[fid * 3 + 2];
        const float* fs = g_face_shape;
        size_t o0 = (size_t)(3 * i0) * B_ + b;
        size_t o1 = (size_t)(3 * i1) * B_ + b;
        size_t o2 = (size_t)(3 * i2) * B_ + b;
        float v1x = fs[o0], v1y = fs[o0 + B_], v1z = fs[o0 + 2 * B_];
        float v2x = fs[o1], v2y = fs[o1 + B_], v2z = fs[o1 + 2 * B_];
        float v3x = fs[o2], v3y = fs[o2 + B_], v3z = fs[o2 + 2 * B_];
        float e1x = v1x - v2x, e1y = v1y - v2y, e1z = v1z - v2z;
        float e2x = v2x - v3x, e2y = v2y - v3y, e2z = v2z - v3z;
        fn[0]      = e1y * e2z - e1z * e2y;
        fn[B_]     = e1z * e2x - e1x * e2z;
        fn[2 * B_] = e1x * e2y - e1y * e2x;
    }
}

__device__ __forceinline__ void color_block(
    int bx, int g, const float* __restrict__ coeff,
    float* __restrict__ dout, float* sm)
{
    const float A0C0   = 0.88622692545275801f;
    const float A1C1   = 1.77245385090551603f;
    const float A2C2   = 2.42703222385900050f;
    const float A2C2D0 = 0.70062326950125306f;
    const float A2C2H  = 1.21351611192950025f;

    float* sc = sm;          // [96][33]
    float* sg = sm + 3200;   // [32][27]
    int t = threadIdx.x;
    int v0 = bx * 32;

    for (int idx = t; idx < 32 * 27; idx += 256) {
        int b_l = idx / 27, kk = idx % 27;
        int k = kk / 3, c = kk % 3;
        float gv = coeff[(size_t)(g * 32 + b_l) * CST + 227 + c * 9 + k];
        if (k == 0) gv += 0.8f;
        sg[b_l * 27 + k * 3 + c] = gv;
    }
    __syncthreads();

    int vslot = t >> 5, b_l = t & 31;
    int b = g * 32 + b_l;
    #pragma unroll
    for (int it = 0; it < 4; it++) {
        int v_l = vslot + it * 8;
        int v = v0 + v_l;
        if (v < NV_) {
            const int4* pb4 = reinterpret_cast<const int4*>(g_pbuf + v * 8);
            int4 pa = pb4[0], pbv = pb4[1];
            int f[8] = {pa.x, pa.y, pa.z, pa.w, pbv.x, pbv.y, pbv.z, pbv.w};
            float sx = 0.f, sy = 0.f, sz = 0.f;
            #pragma unroll
            for (int i = 0; i < 8; i++) {
                const float* fn = g_face_norm + (size_t)(f[i] * 3) * B_ + b;
                sx += fn[0]; sy += fn[B_]; sz += fn[2 * B_];
            }
            float inv = rsqrtf(sx * sx + sy * sy + sz * sz);
            float nx = sx * inv, ny = sy * inv, nz = sz * inv;

            float Y[9];
            Y[0] = A0C0;
            Y[1] = -A1C1 * ny;
            Y[2] =  A1C1 * nz;
            Y[3] = -A1C1 * nx;
            Y[4] =  A2C2 * nx * ny;
            Y[5] = -A2C2 * ny * nz;
            Y[6] =  A2C2D0 * (3.f * nz * nz - 1.f);
            Y[7] = -A2C2 * nx * nz;
            Y[8] =  A2C2H * (nx * nx - ny * ny);

            const float* tx = g_tex + (size_t)(v * 3) * B_ + b;
            #pragma unroll
            for (int c = 0; c < 3; c++) {
                float l = 0.f;
                #pragma unroll
                for (int k = 0; k < 9; k++) l = fmaf(Y[k], sg[b_l * 27 + k * 3 + c], l);
                float col = tx[(size_t)c * B_] * l * (1.f / 255.f);
                sc[(v_l * 3 + c) * 33 + b_l] = fminf(fmaxf(col, 0.f), 1.f);
            }
        }
    }
    __syncthreads();

    int b_l2 = t >> 3, j = t & 7;
    int b2 = g * 32 + b_l2;
    #pragma unroll
    for (int w = 0; w < 4; w++) {
        int v_l = j * 4 + w;
        int v = v0 + v_l;
        if (v < NV_) {
            float* o = dout + OUT_COLOR + (size_t)b2 * NR_ + (size_t)v * 3;
            o[0] = sc[(v_l * 3 + 0) * 33 + b_l2];
            o[1] = sc[(v_l * 3 + 1) * 33 + b_l2];
            o[2] = sc[(v_l * 3 + 2) * 33 + b_l2];
        }
    }
}

__device__ __forceinline__ void tail_block(int bx, float* __restrict__ dout)
{
    int i = bx * 256 + threadIdx.x;
    const int LM_N = B_ * NK_ * 3;
    if (i < LM_N) {
        int d = i % 3, r = i / 3;
        int k = r % NK_, b = r / NK_;
        int v = g_kp[k];
        dout[OUT_LM + i] = dout[(size_t)b * NR_ + (size_t)v * 3 + d];
    } else {
        int q = i - LM_N;
        if (q < NF_ * 3) dout[OUT_TRI + q] = (float)g_tri[q];
    }
}

// ============================================================
// k_mix1: proj blocks + fn(group 0) + fn(group 1)
// ============================================================
__global__ void k_mix1(const float* __restrict__ coeff, float* __restrict__ dout)
{
    __shared__ __align__(16) float sm[3584];
    int bx = blockIdx.x;
    if (bx < NPROJ) {
        proj_block(bx, coeff, dout, sm);
    } else if (bx < NPROJ + NFN) {
        fn_block(bx - NPROJ, 0);
    } else {
        fn_block(bx - NPROJ - NFN, 1);
    }
}

// k_stage(G): color(2G) + color(2G+1) + fn(2G+2) + fn(2G+3)
// (last stage: tail in the fn slot)
__global__ void k_stage(int G, const float* __restrict__ coeff,
                        float* __restrict__ dout)
{
    __shared__ __align__(16) float sm[4096];
    int bx = blockIdx.x;
    if (bx < NCOL) {
        color_block(bx, 2 * G, coeff, dout, sm);
    } else if (bx < 2 * NCOL) {
        color_block(bx - NCOL, 2 * G + 1, coeff, dout, sm);
    } else if (bx < 2 * NCOL + NFN) {
        if (G < 3) fn_block(bx - 2 * NCOL, 2 * G + 2);
        else       tail_block(bx - 2 * NCOL, dout);
    } else if (bx < 2 * NCOL + 2 * NFN) {
        if (G < 3) fn_block(bx - 2 * NCOL - NFN, 2 * G + 3);
    }
}

// ============================================================
extern "C" void kernel_launch(void* const* d_in, const int* in_sizes, int n_in,
                              void* d_out, int out_size)
{
    (void)in_sizes; (void)n_in; (void)out_size;
    const float* coeff     = (const float*)d_in[0];
    const float* meanshape = (const float*)d_in[1];
    const float* idBase    = (const float*)d_in[2];
    const float* exBase    = (const float*)d_in[3];
    const float* meantex   = (const float*)d_in[4];
    const float* texBase   = (const float*)d_in[5];
    const void*  tri       = d_in[6];
    const void*  pbuf      = d_in[7];
    const void*  kp        = d_in[8];
    float* dout = (float*)d_out;

    // fork/join side stream for the texture GEMM (graph-capture-legal
    // event pattern; host objects only, no device allocation)
    cudaStream_t s2;
    cudaStreamCreateWithFlags(&s2, cudaStreamNonBlocking);
    cudaEvent_t evA, evB;
    cudaEventCreateWithFlags(&evA, cudaEventDisableTiming);
    cudaEventCreateWithFlags(&evB, cudaEventDisableTiming);

    k_pre<<<257, 256>>>(tri, pbuf, kp, coeff, meanshape);
    cudaEventRecord(evA, 0);
    cudaStreamWaitEvent(s2, evA, 0);

    k_hmma_tex<<<NT64, 256, 0, s2>>>(texBase, meantex);      // concurrent with shape+mix1
    k_hmma_shape<<<NT64, 256>>>(idBase, exBase, meanshape);
    k_mix1<<<NPROJ + 2 * NFN, 256>>>(coeff, dout);

    cudaEventRecord(evB, s2);
    cudaStreamWaitEvent(0, evB, 0);                           // join before color uses g_tex

    for (int G = 0; G < 3; G++)
        k_stage<<<2 * NCOL + 2 * NFN, 256>>>(G, coeff, dout);
    k_stage<<<2 * NCOL + NFN + NTAIL, 256>>>(3, coeff, dout);
}

// round 16
// speedup vs baseline: 1.1287x; 1.0002x over previous
#include <cuda_runtime.h>
#include <cuda_bf16.h>
#include <math.h>
#include <stdint.h>

#define B_  256
#define NV_ 35709
#define NR_ 107127          // NV*3
#define NF_ 70789
#define NK_ 68
#define CST 257

#define OUT_COLOR ((size_t)B_ * NR_)
#define OUT_LM    ((size_t)2 * B_ * NR_)
#define OUT_TRI   (OUT_LM + (size_t)B_ * NK_ * 3)

#define NPROJ (((NV_ + 31) / 32) * 8)    // 8928 proj blocks
#define NFN   ((NF_ + 1 + 31) / 32)      // 2213 fn blocks per group (32 faces/block)
#define NCOL  ((NV_ + 31) / 32)          // 1116 color blocks per group
#define NT64  ((NR_ + 63) / 64)          // 1674 gemm row tiles
#define NTAIL ((B_ * NK_ * 3 + NF_ * 3 + 255) / 256)

// -------- device scratch --------
__device__ float g_mean[3];
__device__ float g_rot[B_ * 9];
__device__ uint2 g_Bpk[B_ * 112];                          // coeff hi/lo (chunk-permuted)
__device__ float g_face_shape[(size_t)NR_ * B_];           // [row][b]
__device__ float g_tex[(size_t)NR_ * B_];                  // [row][b]
__device__ float g_face_norm[(size_t)(NF_ + 1) * 3 * B_];  // [face*3+d][b]
__device__ int   g_tri[NF_ * 3];
__device__ int4  g_tri4[NF_];                              // padded tri (1 LDG.128/face)
__device__ int   g_pbuf[NV_ * 8];
__device__ int   g_kp[NK_];

// bf16 hi/lo split of a float pair: hi = rn(a),rn(b); lo = rn(residual)
__device__ __forceinline__ void split2(float a, float b, uint32_t& hi, uint32_t& lo) {
    __nv_bfloat16 ah = __float2bfloat16_rn(a), bh = __float2bfloat16_rn(b);
    float ar = a - __bfloat162float(ah), br = b - __bfloat162float(bh);
    __nv_bfloat162 h = __halves2bfloat162(ah, bh);
    __nv_bfloat162 l = __halves2bfloat162(__float2bfloat16_rn(ar), __float2bfloat16_rn(br));
    hi = *reinterpret_cast<uint32_t*>(&h);
    lo = *reinterpret_cast<uint32_t*>(&l);
}

__device__ __forceinline__ uint2 load_split(const float* __restrict__ base,
                                            int kd, size_t row, int pair) {
    float2 v = *reinterpret_cast<const float2*>(base + row * kd + 2 * pair);
    uint32_t hi, lo;
    split2(v.x, v.y, hi, lo);
    return make_uint2(hi, lo);
}

__device__ __forceinline__ void mma_bf16(float* c,
    uint32_t a0, uint32_t a1, uint32_t a2, uint32_t a3,
    uint32_t b0, uint32_t b1)
{
    asm volatile(
        "mma.sync.aligned.m16n8k16.row.col.f32.bf16.bf16.f32 "
        "{%0,%1,%2,%3}, {%4,%5,%6,%7}, {%8,%9}, {%0,%1,%2,%3};"
        : "+f"(c[0]), "+f"(c[1]), "+f"(c[2]), "+f"(c[3])
        : "r"(a0), "r"(a1), "r"(a2), "r"(a3), "r"(b0), "r"(b1));
}

// ============================================================
// k_pre: fused idx-convert + prep + coeffB pack (block-ranged)
// ============================================================
__device__ __forceinline__ void idx_blocks(
    int bx, const void* __restrict__ tri,
    const void* __restrict__ pbuf, const void* __restrict__ kp)
{
    const int* t32 = (const int*)tri;
    bool is64 = true;
    #pragma unroll
    for (int i = 1; i < 32; i += 2) is64 = is64 && (t32[i] == 0);

    int gid = bx * 256 + threadIdx.x;
    int stride = 128 * 256;
    if (is64) {
        const long long* a = (const long long*)tri;
        for (int i = gid; i < NF_ * 3; i += stride) g_tri[i] = (int)a[i];
        for (int i = gid; i < NF_; i += stride)
            g_tri4[i] = make_int4((int)a[3 * i], (int)a[3 * i + 1], (int)a[3 * i + 2], 0);
        const long long* b = (const long long*)pbuf;
        for (int i = gid; i < NV_ * 8; i += stride) g_pbuf[i] = (int)b[i];
        const long long* c = (const long long*)kp;
        for (int i = gid; i < NK_; i += stride) g_kp[i] = (int)c[i];
    } else {
        const int* a = (const int*)tri;
        for (int i = gid; i < NF_ * 3; i += stride) g_tri[i] = a[i];
        for (int i = gid; i < NF_; i += stride)
            g_tri4[i] = make_int4(a[3 * i], a[3 * i + 1], a[3 * i + 2], 0);
        const int* b = (const int*)pbuf;
        for (int i = gid; i < NV_ * 8; i += stride) g_pbuf[i] = b[i];
        const int* c = (const int*)kp;
        for (int i = gid; i < NK_; i += stride) g_kp[i] = c[i];
    }
}

__device__ __forceinline__ void prep_block(
    const float* __restrict__ coeff, const float* __restrict__ meanshape,
    float* sm)
{
    float* rx = sm, *ry = sm + 256, *rz = sm + 512;
    int t = threadIdx.x;
    float s0 = 0.f, s1 = 0.f, s2 = 0.f;
    for (int v = t; v < NV_; v += 256) {
        s0 += meanshape[v * 3 + 0];
        s1 += meanshape[v * 3 + 1];
        s2 += meanshape[v * 3 + 2];
    }
    rx[t] = s0; ry[t] = s1; rz[t] = s2;
    __syncthreads();
    for (int off = 128; off > 0; off >>= 1) {
        if (t < off) { rx[t] += rx[t + off]; ry[t] += ry[t + off]; rz[t] += rz[t + off]; }
        __syncthreads();
    }
    if (t == 0) {
        g_mean[0] = rx[0] / (float)NV_;
        g_mean[1] = ry[0] / (float)NV_;
        g_mean[2] = rz[0] / (float)NV_;
    }
    float ax = coeff[t * CST + 224], ay = coeff[t * CST + 225], az = coeff[t * CST + 226];
    float sx = sinf(ax), cx = cosf(ax);
    float sy = sinf(ay), cy = cosf(ay);
    float sz = sinf(az), cz = cosf(az);
    float* M = g_rot + t * 9;
    M[0] = cz * cy;  M[1] = cz * sy * sx - sz * cx;  M[2] = cz * sy * cx + sz * sx;
    M[3] = sz * cy;  M[4] = sz * sy * sx + cz * cx;  M[5] = sz * sy * cx - cz * sx;
    M[6] = -sy;      M[7] = cy * sx;                 M[8] = cy * cx;
}

__device__ __forceinline__ void coeffB_block(int bx, const float* __restrict__ coeff)
{
    int t = threadIdx.x;
    if (t >= 224) return;
    int b = bx * 2 + t / 112;
    int c = t % 112;
    float x = coeff[b * CST + 2 * c];
    float y = coeff[b * CST + 2 * c + 1];
    uint32_t hi, lo;
    split2(x, y, hi, lo);
    int w = c & 7;
    int pos = (c & ~7) + ((w & 3) * 2 + (w >> 2));
    g_Bpk[b * 112 + pos] = make_uint2(hi, lo);
}

__global__ void k_pre(const void* __restrict__ tri,
                      const void* __restrict__ pbuf,
                      const void* __restrict__ kp,
                      const float* __restrict__ coeff,
                      const float* __restrict__ meanshape)
{
    __shared__ float sm[768];
    int bx = blockIdx.x;
    if (bx < 128) {
        idx_blocks(bx, tri, pbuf, kp);
    } else if (bx == 128) {
        prep_block(coeff, meanshape, sm);
    } else {
        coeffB_block(bx - 129, coeff);
    }
}

// ============================================================
// gemm_tile: bf16-split tensor-core GEMM tile (round-9 config).
// ============================================================
__device__ __forceinline__ void gemm_tile(
    int tile, bool is_shape,
    const float* __restrict__ idBase, const float* __restrict__ exBase,
    const float* __restrict__ texBase,
    const float* __restrict__ meanshape, const float* __restrict__ meantex)
{
    int t = threadIdx.x;
    int w = t >> 5, lane = t & 31;
    int g = lane >> 2, tig = lane & 3;
    int wm = w & 1, wn = w >> 1;
    int r0 = tile * 64;
    int nch = is_shape ? 9 : 5;
    int kboff = is_shape ? 0 : 72;

    int rw0 = r0 + wm * 32 + g;
    int rows[4] = {rw0, rw0 + 8, rw0 + 16, rw0 + 24};
    size_t lrows[4];
    #pragma unroll
    for (int s = 0; s < 4; ++s)
        lrows[s] = (size_t)(rows[s] < NR_ ? rows[s] : NR_ - 1);
    int n0 = wn * 64;

    float acc[8][8];
    #pragma unroll
    for (int j = 0; j < 8; ++j)
        #pragma unroll
        for (int q = 0; q < 8; ++q) acc[j][q] = 0.f;

    for (int c = 0; c < nch; ++c) {
        int kw = c * 8;
        const float* ab;
        int kd, poff;
        if (is_shape) {
            if (c < 5) { ab = idBase; kd = 80; poff = 0; }
            else       { ab = exBase; kd = 64; poff = 40; }
        } else       { ab = texBase; kd = 80; poff = 0; }
        int p0 = kw + tig - poff;
        uint2 a00 = load_split(ab, kd, lrows[0], p0);
        uint2 a01 = load_split(ab, kd, lrows[1], p0);
        uint2 a02 = load_split(ab, kd, lrows[0], p0 + 4);
        uint2 a03 = load_split(ab, kd, lrows[1], p0 + 4);
        uint2 a10 = load_split(ab, kd, lrows[2], p0);
        uint2 a11 = load_split(ab, kd, lrows[3], p0);
        uint2 a12 = load_split(ab, kd, lrows[2], p0 + 4);
        uint2 a13 = load_split(ab, kd, lrows[3], p0 + 4);

        const uint2* bbase = g_Bpk + (size_t)(n0 + g) * 112 + kboff + kw + 2 * tig;
        #pragma unroll
        for (int j = 0; j < 8; ++j) {
            uint4 bv = *reinterpret_cast<const uint4*>(bbase + (size_t)j * 8 * 112);
            mma_bf16(&acc[j][0], a00.x, a01.x, a02.x, a03.x, bv.x, bv.z);
            mma_bf16(&acc[j][0], a00.x, a01.x, a02.x, a03.x, bv.y, bv.w);
            mma_bf16(&acc[j][0], a00.y, a01.y, a02.y, a03.y, bv.x, bv.z);
            mma_bf16(&acc[j][4], a10.x, a11.x, a12.x, a13.x, bv.x, bv.z);
            mma_bf16(&acc[j][4], a10.x, a11.x, a12.x, a13.x, bv.y, bv.w);
            mma_bf16(&acc[j][4], a10.y, a11.y, a12.y, a13.y, bv.x, bv.z);
        }
    }

    float addv[4];
    float* dst;
    if (is_shape) {
        #pragma unroll
        for (int s = 0; s < 4; ++s)
            addv[s] = (rows[s] < NR_) ? meanshape[rows[s]] - g_mean[rows[s] % 3] : 0.f;
        dst = g_face_shape;
    } else {
        #pragma unroll
        for (int s = 0; s < 4; ++s)
            addv[s] = (rows[s] < NR_) ? meantex[rows[s]] : 0.f;
        dst = g_tex;
    }
    #pragma unroll
    for (int j = 0; j < 8; ++j) {
        int col = n0 + j * 8 + 2 * tig;
        #pragma unroll
        for (int s = 0; s < 4; ++s) {
            if (rows[s] < NR_) {
                int base = (s >> 1) * 4 + (s & 1) * 2;
                *reinterpret_cast<float2*>(dst + (size_t)rows[s] * B_ + col) =
                    make_float2(acc[j][base] + addv[s], acc[j][base + 1] + addv[s]);
            }
        }
    }
}

__global__ __launch_bounds__(256, 2) void k_hmma_shape(
    const float* __restrict__ idBase, const float* __restrict__ exBase,
    const float* __restrict__ meanshape)
{
    gemm_tile(blockIdx.x, true, idBase, exBase, (const float*)0, meanshape, (const float*)0);
}

__global__ __launch_bounds__(256, 2) void k_hmma_tex(
    const float* __restrict__ texBase, const float* __restrict__ meantex)
{
    gemm_tile(blockIdx.x, false, (const float*)0, (const float*)0, texBase, (const float*)0, meantex);
}

// ============================================================
// gather-phase device blocks
// ============================================================
__device__ __forceinline__ void proj_block(
    int bx, const float* __restrict__ coeff, float* __restrict__ dout, float* sm)
{
    float* s    = sm;          // [96][33]
    float* srot = sm + 3200;   // [32][12]
    int t = threadIdx.x;
    int g = bx % 8;
    int v0 = (bx / 8) * 32;
    int r0 = v0 * 3;

    for (int idx = t; idx < 32 * 12; idx += 256) {
        int b_l = idx / 12, k = idx % 12;
        int b = g * 32 + b_l;
        srot[b_l * 12 + k] = (k < 9) ? g_rot[b * 9 + k] : coeff[b * CST + 254 + (k - 9)];
    }
    #pragma unroll
    for (int it = 0; it < 12; it++) {
        int idx = t + it * 256;
        int row = idx >> 5, b_l = idx & 31;
        s[row * 33 + b_l] = (r0 + row < NR_) ?
            g_face_shape[(size_t)(r0 + row) * B_ + g * 32 + b_l] : 0.f;
    }
    __syncthreads();

    int b_l = t >> 3, j = t & 7;
    int b = g * 32 + b_l;
    float m0 = srot[b_l * 12 + 0], m1 = srot[b_l * 12 + 1], m2 = srot[b_l * 12 + 2];
    float m3 = srot[b_l * 12 + 3], m4 = srot[b_l * 12 + 4], m5 = srot[b_l * 12 + 5];
    float m6 = srot[b_l * 12 + 6], m7 = srot[b_l * 12 + 7], m8 = srot[b_l * 12 + 8];
    float tx = srot[b_l * 12 + 9], ty = srot[b_l * 12 + 10], tz = srot[b_l * 12 + 11];
    #pragma unroll
    for (int w = 0; w < 4; w++) {
        int v_l = j * 4 + w;
        int v = v0 + v_l;
        if (v < NV_) {
            float x = s[(v_l * 3 + 0) * 33 + b_l];
            float y = s[(v_l * 3 + 1) * 33 + b_l];
            float z = s[(v_l * 3 + 2) * 33 + b_l];
            float* o = dout + (size_t)b * NR_ + (size_t)v * 3;
            o[0] = fmaf(m0, x, fmaf(m1, y, fmaf(m2, z, tx)));
            o[1] = fmaf(m3, x, fmaf(m4, y, fmaf(m5, z, ty)));
            o[2] = fmaf(m6, x, fmaf(m7, y, fmaf(m8, z, tz)));
        }
    }
}

__device__ __forceinline__ void fn_block(int bx, int g)
{
    int t = threadIdx.x;
    int quad = bx * 8 + (t >> 5);
    int b = g * 32 + (t & 31);
    int fid0 = quad * 4;

    // prefetch indices for all 4 faces (breaks index->data serial chain)
    int4 tr[4];
    #pragma unroll
    for (int u = 0; u < 4; u++) {
        int fid = fid0 + u;
        tr[u] = (fid < NF_) ? g_tri4[fid] : make_int4(0, 0, 0, 0);
    }

    #pragma unroll
    for (int u = 0; u < 4; u++) {
        int fid = fid0 + u;
        if (fid > NF_) continue;
        float* fn = g_face_norm + (size_t)(fid * 3) * B_ + b;
        if (fid == NF_) {
            fn[0] = 0.f; fn[B_] = 0.f; fn[2 * B_] = 0.f;
            continue;
        }
        const float* fs = g_face_shape;
        size_t o0 = (size_t)(3 * tr[u].x) * B_ + b;
        size_t o1 = (size_t)(3 * tr[u].y) * B_ + b;
        size_t o2 = (size_t)(3 * tr[u].z) * B_ + b;
        float v1x = fs[o0], v1y = fs[o0 + B_], v1z = fs[o0 + 2 * B_];
        float v2x = fs[o1], v2y = fs[o1 + B_], v2z = fs[o1 + 2 * B_];
        float v3x = fs[o2], v3y = fs[o2 + B_], v3z = fs[o2 + 2 * B_];
        float e1x = v1x - v2x, e1y = v1y - v2y, e1z = v1z - v2z;
        float e2x = v2x - v3x, e2y = v2y - v3y, e2z = v2z - v3z;
        fn[0]      = e1y * e2z - e1z * e2y;
        fn[B_]     = e1z * e2x - e1x * e2z;
        fn[2 * B_] = e1x * e2y - e1y * e2x;
    }
}

__device__ __forceinline__ void color_block(
    int bx, int g, const float* __restrict__ coeff,
    float* __restrict__ dout, float* sm)
{
    const float A0C0   = 0.88622692545275801f;
    const float A1C1   = 1.77245385090551603f;
    const float A2C2   = 2.42703222385900050f;
    const float A2C2D0 = 0.70062326950125306f;
    const float A2C2H  = 1.21351611192950025f;

    float* sc = sm;          // [96][33]
    float* sg = sm + 3200;   // [32][27]
    int t = threadIdx.x;
    int v0 = bx * 32;

    for (int idx = t; idx < 32 * 27; idx += 256) {
        int b_l = idx / 27, kk = idx % 27;
        int k = kk / 3, c = kk % 3;
        float gv = coeff[(size_t)(g * 32 + b_l) * CST + 227 + c * 9 + k];
        if (k == 0) gv += 0.8f;
        sg[b_l * 27 + k * 3 + c] = gv;
    }
    __syncthreads();

    int vslot = t >> 5, b_l = t & 31;
    int b = g * 32 + b_l;
    #pragma unroll
    for (int it = 0; it < 4; it++) {
        int v_l = vslot + it * 8;
        int v = v0 + v_l;
        if (v < NV_) {
            const int4* pb4 = reinterpret_cast<const int4*>(g_pbuf + v * 8);
            int4 pa = pb4[0], pbv = pb4[1];
            int f[8] = {pa.x, pa.y, pa.z, pa.w, pbv.x, pbv.y, pbv.z, pbv.w};
            // load-all-then-reduce: keep all 24 gather loads in flight
            float fx[8], fy[8], fz[8];
            #pragma unroll
            for (int i = 0; i < 8; i++) {
                const float* fn = g_face_norm + (size_t)(f[i] * 3) * B_ + b;
                fx[i] = fn[0]; fy[i] = fn[B_]; fz[i] = fn[2 * B_];
            }
            float sx = 0.f, sy = 0.f, sz = 0.f;
            #pragma unroll
            for (int i = 0; i < 8; i++) { sx += fx[i]; sy += fy[i]; sz += fz[i]; }
            float inv = rsqrtf(sx * sx + sy * sy + sz * sz);
            float nx = sx * inv, ny = sy * inv, nz = sz * inv;

            float Y[9];
            Y[0] = A0C0;
            Y[1] = -A1C1 * ny;
            Y[2] =  A1C1 * nz;
            Y[3] = -A1C1 * nx;
            Y[4] =  A2C2 * nx * ny;
            Y[5] = -A2C2 * ny * nz;
            Y[6] =  A2C2D0 * (3.f * nz * nz - 1.f);
            Y[7] = -A2C2 * nx * nz;
            Y[8] =  A2C2H * (nx * nx - ny * ny);

            const float* tx = g_tex + (size_t)(v * 3) * B_ + b;
            #pragma unroll
            for (int c = 0; c < 3; c++) {
                float l = 0.f;
                #pragma unroll
                for (int k = 0; k < 9; k++) l = fmaf(Y[k], sg[b_l * 27 + k * 3 + c], l);
                float col = tx[(size_t)c * B_] * l * (1.f / 255.f);
                sc[(v_l * 3 + c) * 33 + b_l] = fminf(fmaxf(col, 0.f), 1.f);
            }
        }
    }
    __syncthreads();

    int b_l2 = t >> 3, j = t & 7;
    int b2 = g * 32 + b_l2;
    #pragma unroll
    for (int w = 0; w < 4; w++) {
        int v_l = j * 4 + w;
        int v = v0 + v_l;
        if (v < NV_) {
            float* o = dout + OUT_COLOR + (size_t)b2 * NR_ + (size_t)v * 3;
            o[0] = sc[(v_l * 3 + 0) * 33 + b_l2];
            o[1] = sc[(v_l * 3 + 1) * 33 + b_l2];
            o[2] = sc[(v_l * 3 + 2) * 33 + b_l2];
        }
    }
}

__device__ __forceinline__ void tail_block(int bx, float* __restrict__ dout)
{
    int i = bx * 256 + threadIdx.x;
    const int LM_N = B_ * NK_ * 3;
    if (i < LM_N) {
        int d = i % 3, r = i / 3;
        int k = r % NK_, b = r / NK_;
        int v = g_kp[k];
        dout[OUT_LM + i] = dout[(size_t)b * NR_ + (size_t)v * 3 + d];
    } else {
        int q = i - LM_N;
        if (q < NF_ * 3) dout[OUT_TRI + q] = (float)g_tri[q];
    }
}

// ============================================================
// k_mix1: proj blocks + fn(group 0) + fn(group 1)
// ============================================================
__global__ void k_mix1(const float* __restrict__ coeff, float* __restrict__ dout)
{
    __shared__ __align__(16) float sm[3584];
    int bx = blockIdx.x;
    if (bx < NPROJ) {
        proj_block(bx, coeff, dout, sm);
    } else if (bx < NPROJ + NFN) {
        fn_block(bx - NPROJ, 0);
    } else {
        fn_block(bx - NPROJ - NFN, 1);
    }
}

// k_stage(G): color(2G) + color(2G+1) + fn(2G+2) + fn(2G+3)
// launch_bounds(256,4): allow 64 regs so the 24 gather loads stay in flight
__global__ __launch_bounds__(256, 4) void k_stage(
    int G, const float* __restrict__ coeff, float* __restrict__ dout)
{
    __shared__ __align__(16) float sm[4096];
    int bx = blockIdx.x;
    if (bx < NCOL) {
        color_block(bx, 2 * G, coeff, dout, sm);
    } else if (bx < 2 * NCOL) {
        color_block(bx - NCOL, 2 * G + 1, coeff, dout, sm);
    } else if (bx < 2 * NCOL + NFN) {
        if (G < 3) fn_block(bx - 2 * NCOL, 2 * G + 2);
        else       tail_block(bx - 2 * NCOL, dout);
    } else if (bx < 2 * NCOL + 2 * NFN) {
        if (G < 3) fn_block(bx - 2 * NCOL - NFN, 2 * G + 3);
    }
}

// ============================================================
extern "C" void kernel_launch(void* const* d_in, const int* in_sizes, int n_in,
                              void* d_out, int out_size)
{
    (void)in_sizes; (void)n_in; (void)out_size;
    const float* coeff     = (const float*)d_in[0];
    const float* meanshape = (const float*)d_in[1];
    const float* idBase    = (const float*)d_in[2];
    const float* exBase    = (const float*)d_in[3];
    const float* meantex   = (const float*)d_in[4];
    const float* texBase   = (const float*)d_in[5];
    const void*  tri       = d_in[6];
    const void*  pbuf      = d_in[7];
    const void*  kp        = d_in[8];
    float* dout = (float*)d_out;

    cudaStream_t s2;
    cudaStreamCreateWithFlags(&s2, cudaStreamNonBlocking);
    cudaEvent_t evA, evB;
    cudaEventCreateWithFlags(&evA, cudaEventDisableTiming);
    cudaEventCreateWithFlags(&evB, cudaEventDisableTiming);

    k_pre<<<257, 256>>>(tri, pbuf, kp, coeff, meanshape);
    cudaEventRecord(evA, 0);
    cudaStreamWaitEvent(s2, evA, 0);

    k_hmma_tex<<<NT64, 256, 0, s2>>>(texBase, meantex);
    k_hmma_shape<<<NT64, 256>>>(idBase, exBase, meanshape);
    k_mix1<<<NPROJ + 2 * NFN, 256>>>(coeff, dout);

    cudaEventRecord(evB, s2);
    cudaStreamWaitEvent(0, evB, 0);

    for (int G = 0; G < 3; G++)
        k_stage<<<2 * NCOL + 2 * NFN, 256>>>(G, coeff, dout);
    k_stage<<<2 * NCOL + NFN + NTAIL, 256>>>(3, coeff, dout);
}

// round 17
// speedup vs baseline: 1.1523x; 1.0210x over previous
#include <cuda_runtime.h>
#include <cuda_bf16.h>
#include <cuda_fp16.h>
#include <math.h>
#include <stdint.h>

#define B_  256
#define NV_ 35709
#define NR_ 107127          // NV*3
#define NF_ 70789
#define NK_ 68
#define CST 257

#define OUT_COLOR ((size_t)B_ * NR_)
#define OUT_LM    ((size_t)2 * B_ * NR_)
#define OUT_TRI   (OUT_LM + (size_t)B_ * NK_ * 3)

#define NPROJ (((NV_ + 31) / 32) * 8)    // 8928 proj blocks
#define NFN   ((NF_ + 1 + 31) / 32)      // 2213 fn blocks per group (32 faces/block)
#define NCOL  ((NV_ + 31) / 32)          // 1116 color blocks per group
#define NT64  ((NR_ + 63) / 64)          // 1674 gemm row tiles
#define NTAIL ((B_ * NK_ * 3 + NF_ * 3 + 255) / 256)

// -------- device scratch --------
__device__ float g_mean[3];
__device__ float g_rot[B_ * 9];
__device__ uint2 g_Bpk[B_ * 112];                          // coeff hi/lo (chunk-permuted)
__device__ float g_face_shape[(size_t)NR_ * B_];           // [row][b]
__device__ float g_tex[(size_t)NR_ * B_];                  // [row][b]
__device__ __half g_face_norm[(size_t)(NF_ + 1) * 3 * B_]; // [face*3+d][b], fp16
__device__ int   g_tri[NF_ * 3];
__device__ int4  g_tri4[NF_];                              // padded tri (1 LDG.128/face)
__device__ int   g_pbuf[NV_ * 8];
__device__ int   g_kp[NK_];

// bf16 hi/lo split of a float pair: hi = rn(a),rn(b); lo = rn(residual)
__device__ __forceinline__ void split2(float a, float b, uint32_t& hi, uint32_t& lo) {
    __nv_bfloat16 ah = __float2bfloat16_rn(a), bh = __float2bfloat16_rn(b);
    float ar = a - __bfloat162float(ah), br = b - __bfloat162float(bh);
    __nv_bfloat162 h = __halves2bfloat162(ah, bh);
    __nv_bfloat162 l = __halves2bfloat162(__float2bfloat16_rn(ar), __float2bfloat16_rn(br));
    hi = *reinterpret_cast<uint32_t*>(&h);
    lo = *reinterpret_cast<uint32_t*>(&l);
}

__device__ __forceinline__ uint2 load_split(const float* __restrict__ base,
                                            int kd, size_t row, int pair) {
    float2 v = *reinterpret_cast<const float2*>(base + row * kd + 2 * pair);
    uint32_t hi, lo;
    split2(v.x, v.y, hi, lo);
    return make_uint2(hi, lo);
}

__device__ __forceinline__ void mma_bf16(float* c,
    uint32_t a0, uint32_t a1, uint32_t a2, uint32_t a3,
    uint32_t b0, uint32_t b1)
{
    asm volatile(
        "mma.sync.aligned.m16n8k16.row.col.f32.bf16.bf16.f32 "
        "{%0,%1,%2,%3}, {%4,%5,%6,%7}, {%8,%9}, {%0,%1,%2,%3};"
        : "+f"(c[0]), "+f"(c[1]), "+f"(c[2]), "+f"(c[3])
        : "r"(a0), "r"(a1), "r"(a2), "r"(a3), "r"(b0), "r"(b1));
}

// ============================================================
// k_pre: fused idx-convert + prep + coeffB pack (block-ranged)
// ============================================================
__device__ __forceinline__ void idx_blocks(
    int bx, const void* __restrict__ tri,
    const void* __restrict__ pbuf, const void* __restrict__ kp)
{
    const int* t32 = (const int*)tri;
    bool is64 = true;
    #pragma unroll
    for (int i = 1; i < 32; i += 2) is64 = is64 && (t32[i] == 0);

    int gid = bx * 256 + threadIdx.x;
    int stride = 128 * 256;
    if (is64) {
        const long long* a = (const long long*)tri;
        for (int i = gid; i < NF_ * 3; i += stride) g_tri[i] = (int)a[i];
        for (int i = gid; i < NF_; i += stride)
            g_tri4[i] = make_int4((int)a[3 * i], (int)a[3 * i + 1], (int)a[3 * i + 2], 0);
        const long long* b = (const long long*)pbuf;
        for (int i = gid; i < NV_ * 8; i += stride) g_pbuf[i] = (int)b[i];
        const long long* c = (const long long*)kp;
        for (int i = gid; i < NK_; i += stride) g_kp[i] = (int)c[i];
    } else {
        const int* a = (const int*)tri;
        for (int i = gid; i < NF_ * 3; i += stride) g_tri[i] = a[i];
        for (int i = gid; i < NF_; i += stride)
            g_tri4[i] = make_int4(a[3 * i], a[3 * i + 1], a[3 * i + 2], 0);
        const int* b = (const int*)pbuf;
        for (int i = gid; i < NV_ * 8; i += stride) g_pbuf[i] = b[i];
        const int* c = (const int*)kp;
        for (int i = gid; i < NK_; i += stride) g_kp[i] = c[i];
    }
}

__device__ __forceinline__ void prep_block(
    const float* __restrict__ coeff, const float* __restrict__ meanshape,
    float* sm)
{
    float* rx = sm, *ry = sm + 256, *rz = sm + 512;
    int t = threadIdx.x;
    float s0 = 0.f, s1 = 0.f, s2 = 0.f;
    for (int v = t; v < NV_; v += 256) {
        s0 += meanshape[v * 3 + 0];
        s1 += meanshape[v * 3 + 1];
        s2 += meanshape[v * 3 + 2];
    }
    rx[t] = s0; ry[t] = s1; rz[t] = s2;
    __syncthreads();
    for (int off = 128; off > 0; off >>= 1) {
        if (t < off) { rx[t] += rx[t + off]; ry[t] += ry[t + off]; rz[t] += rz[t + off]; }
        __syncthreads();
    }
    if (t == 0) {
        g_mean[0] = rx[0] / (float)NV_;
        g_mean[1] = ry[0] / (float)NV_;
        g_mean[2] = rz[0] / (float)NV_;
    }
    float ax = coeff[t * CST + 224], ay = coeff[t * CST + 225], az = coeff[t * CST + 226];
    float sx = sinf(ax), cx = cosf(ax);
    float sy = sinf(ay), cy = cosf(ay);
    float sz = sinf(az), cz = cosf(az);
    float* M = g_rot + t * 9;
    M[0] = cz * cy;  M[1] = cz * sy * sx - sz * cx;  M[2] = cz * sy * cx + sz * sx;
    M[3] = sz * cy;  M[4] = sz * sy * sx + cz * cx;  M[5] = sz * sy * cx - cz * sx;
    M[6] = -sy;      M[7] = cy * sx;                 M[8] = cy * cx;
}

__device__ __forceinline__ void coeffB_block(int bx, const float* __restrict__ coeff)
{
    int t = threadIdx.x;
    if (t >= 224) return;
    int b = bx * 2 + t / 112;
    int c = t % 112;
    float x = coeff[b * CST + 2 * c];
    float y = coeff[b * CST + 2 * c + 1];
    uint32_t hi, lo;
    split2(x, y, hi, lo);
    int w = c & 7;
    int pos = (c & ~7) + ((w & 3) * 2 + (w >> 2));
    g_Bpk[b * 112 + pos] = make_uint2(hi, lo);
}

__global__ void k_pre(const void* __restrict__ tri,
                      const void* __restrict__ pbuf,
                      const void* __restrict__ kp,
                      const float* __restrict__ coeff,
                      const float* __restrict__ meanshape)
{
    __shared__ float sm[768];
    int bx = blockIdx.x;
    if (bx < 128) {
        idx_blocks(bx, tri, pbuf, kp);
    } else if (bx == 128) {
        prep_block(coeff, meanshape, sm);
    } else {
        coeffB_block(bx - 129, coeff);
    }
}

// ============================================================
// gemm_tile: bf16-split tensor-core GEMM tile (round-9 config).
// ============================================================
__device__ __forceinline__ void gemm_tile(
    int tile, bool is_shape,
    const float* __restrict__ idBase, const float* __restrict__ exBase,
    const float* __restrict__ texBase,
    const float* __restrict__ meanshape, const float* __restrict__ meantex)
{
    int t = threadIdx.x;
    int w = t >> 5, lane = t & 31;
    int g = lane >> 2, tig = lane & 3;
    int wm = w & 1, wn = w >> 1;
    int r0 = tile * 64;
    int nch = is_shape ? 9 : 5;
    int kboff = is_shape ? 0 : 72;

    int rw0 = r0 + wm * 32 + g;
    int rows[4] = {rw0, rw0 + 8, rw0 + 16, rw0 + 24};
    size_t lrows[4];
    #pragma unroll
    for (int s = 0; s < 4; ++s)
        lrows[s] = (size_t)(rows[s] < NR_ ? rows[s] : NR_ - 1);
    int n0 = wn * 64;

    float acc[8][8];
    #pragma unroll
    for (int j = 0; j < 8; ++j)
        #pragma unroll
        for (int q = 0; q < 8; ++q) acc[j][q] = 0.f;

    for (int c = 0; c < nch; ++c) {
        int kw = c * 8;
        const float* ab;
        int kd, poff;
        if (is_shape) {
            if (c < 5) { ab = idBase; kd = 80; poff = 0; }
            else       { ab = exBase; kd = 64; poff = 40; }
        } else       { ab = texBase; kd = 80; poff = 0; }
        int p0 = kw + tig - poff;
        uint2 a00 = load_split(ab, kd, lrows[0], p0);
        uint2 a01 = load_split(ab, kd, lrows[1], p0);
        uint2 a02 = load_split(ab, kd, lrows[0], p0 + 4);
        uint2 a03 = load_split(ab, kd, lrows[1], p0 + 4);
        uint2 a10 = load_split(ab, kd, lrows[2], p0);
        uint2 a11 = load_split(ab, kd, lrows[3], p0);
        uint2 a12 = load_split(ab, kd, lrows[2], p0 + 4);
        uint2 a13 = load_split(ab, kd, lrows[3], p0 + 4);

        const uint2* bbase = g_Bpk + (size_t)(n0 + g) * 112 + kboff + kw + 2 * tig;
        #pragma unroll
        for (int j = 0; j < 8; ++j) {
            uint4 bv = *reinterpret_cast<const uint4*>(bbase + (size_t)j * 8 * 112);
            mma_bf16(&acc[j][0], a00.x, a01.x, a02.x, a03.x, bv.x, bv.z);
            mma_bf16(&acc[j][0], a00.x, a01.x, a02.x, a03.x, bv.y, bv.w);
            mma_bf16(&acc[j][0], a00.y, a01.y, a02.y, a03.y, bv.x, bv.z);
            mma_bf16(&acc[j][4], a10.x, a11.x, a12.x, a13.x, bv.x, bv.z);
            mma_bf16(&acc[j][4], a10.x, a11.x, a12.x, a13.x, bv.y, bv.w);
            mma_bf16(&acc[j][4], a10.y, a11.y, a12.y, a13.y, bv.x, bv.z);
        }
    }

    float addv[4];
    float* dst;
    if (is_shape) {
        #pragma unroll
        for (int s = 0; s < 4; ++s)
            addv[s] = (rows[s] < NR_) ? meanshape[rows[s]] - g_mean[rows[s] % 3] : 0.f;
        dst = g_face_shape;
    } else {
        #pragma unroll
        for (int s = 0; s < 4; ++s)
            addv[s] = (rows[s] < NR_) ? meantex[rows[s]] : 0.f;
        dst = g_tex;
    }
    #pragma unroll
    for (int j = 0; j < 8; ++j) {
        int col = n0 + j * 8 + 2 * tig;
        #pragma unroll
        for (int s = 0; s < 4; ++s) {
            if (rows[s] < NR_) {
                int base = (s >> 1) * 4 + (s & 1) * 2;
                *reinterpret_cast<float2*>(dst + (size_t)rows[s] * B_ + col) =
                    make_float2(acc[j][base] + addv[s], acc[j][base + 1] + addv[s]);
            }
        }
    }
}

__global__ __launch_bounds__(256, 2) void k_hmma_shape(
    const float* __restrict__ idBase, const float* __restrict__ exBase,
    const float* __restrict__ meanshape)
{
    gemm_tile(blockIdx.x, true, idBase, exBase, (const float*)0, meanshape, (const float*)0);
}

__global__ __launch_bounds__(256, 2) void k_hmma_tex(
    const float* __restrict__ texBase, const float* __restrict__ meantex)
{
    gemm_tile(blockIdx.x, false, (const float*)0, (const float*)0, texBase, (const float*)0, meantex);
}

// ============================================================
// gather-phase device blocks
// ============================================================
__device__ __forceinline__ void proj_block(
    int bx, const float* __restrict__ coeff, float* __restrict__ dout, float* sm)
{
    float* s    = sm;          // [96][33]
    float* srot = sm + 3200;   // [32][12]
    int t = threadIdx.x;
    int g = bx % 8;
    int v0 = (bx / 8) * 32;
    int r0 = v0 * 3;

    for (int idx = t; idx < 32 * 12; idx += 256) {
        int b_l = idx / 12, k = idx % 12;
        int b = g * 32 + b_l;
        srot[b_l * 12 + k] = (k < 9) ? g_rot[b * 9 + k] : coeff[b * CST + 254 + (k - 9)];
    }
    #pragma unroll
    for (int it = 0; it < 12; it++) {
        int idx = t + it * 256;
        int row = idx >> 5, b_l = idx & 31;
        s[row * 33 + b_l] = (r0 + row < NR_) ?
            g_face_shape[(size_t)(r0 + row) * B_ + g * 32 + b_l] : 0.f;
    }
    __syncthreads();

    int b_l = t >> 3, j = t & 7;
    int b = g * 32 + b_l;
    float m0 = srot[b_l * 12 + 0], m1 = srot[b_l * 12 + 1], m2 = srot[b_l * 12 + 2];
    float m3 = srot[b_l * 12 + 3], m4 = srot[b_l * 12 + 4], m5 = srot[b_l * 12 + 5];
    float m6 = srot[b_l * 12 + 6], m7 = srot[b_l * 12 + 7], m8 = srot[b_l * 12 + 8];
    float tx = srot[b_l * 12 + 9], ty = srot[b_l * 12 + 10], tz = srot[b_l * 12 + 11];
    #pragma unroll
    for (int w = 0; w < 4; w++) {
        int v_l = j * 4 + w;
        int v = v0 + v_l;
        if (v < NV_) {
            float x = s[(v_l * 3 + 0) * 33 + b_l];
            float y = s[(v_l * 3 + 1) * 33 + b_l];
            float z = s[(v_l * 3 + 2) * 33 + b_l];
            float* o = dout + (size_t)b * NR_ + (size_t)v * 3;
            o[0] = fmaf(m0, x, fmaf(m1, y, fmaf(m2, z, tx)));
            o[1] = fmaf(m3, x, fmaf(m4, y, fmaf(m5, z, ty)));
            o[2] = fmaf(m6, x, fmaf(m7, y, fmaf(m8, z, tz)));
        }
    }
}

__device__ __forceinline__ void fn_block(int bx, int g)
{
    int t = threadIdx.x;
    int quad = bx * 8 + (t >> 5);
    int b = g * 32 + (t & 31);
    int fid0 = quad * 4;

    int4 tr[4];
    #pragma unroll
    for (int u = 0; u < 4; u++) {
        int fid = fid0 + u;
        tr[u] = (fid < NF_) ? g_tri4[fid] : make_int4(0, 0, 0, 0);
    }

    #pragma unroll
    for (int u = 0; u < 4; u++) {
        int fid = fid0 + u;
        if (fid > NF_) continue;
        __half* fn = g_face_norm + (size_t)(fid * 3) * B_ + b;
        if (fid == NF_) {
            fn[0] = __float2half(0.f);
            fn[B_] = __float2half(0.f);
            fn[2 * B_] = __float2half(0.f);
            continue;
        }
        const float* fs = g_face_shape;
        size_t o0 = (size_t)(3 * tr[u].x) * B_ + b;
        size_t o1 = (size_t)(3 * tr[u].y) * B_ + b;
        size_t o2 = (size_t)(3 * tr[u].z) * B_ + b;
        float v1x = fs[o0], v1y = fs[o0 + B_], v1z = fs[o0 + 2 * B_];
        float v2x = fs[o1], v2y = fs[o1 + B_], v2z = fs[o1 + 2 * B_];
        float v3x = fs[o2], v3y = fs[o2 + B_], v3z = fs[o2 + 2 * B_];
        float e1x = v1x - v2x, e1y = v1y - v2y, e1z = v1z - v2z;
        float e2x = v2x - v3x, e2y = v2y - v3y, e2z = v2z - v3z;
        fn[0]      = __float2half(e1y * e2z - e1z * e2y);
        fn[B_]     = __float2half(e1z * e2x - e1x * e2z);
        fn[2 * B_] = __float2half(e1x * e2y - e1y * e2x);
    }
}

__device__ __forceinline__ void color_block(
    int bx, int g, const float* __restrict__ coeff,
    float* __restrict__ dout, float* sm)
{
    const float A0C0   = 0.88622692545275801f;
    const float A1C1   = 1.77245385090551603f;
    const float A2C2   = 2.42703222385900050f;
    const float A2C2D0 = 0.70062326950125306f;
    const float A2C2H  = 1.21351611192950025f;

    float* sc = sm;          // [96][33]
    float* sg = sm + 3200;   // [32][27]
    int t = threadIdx.x;
    int v0 = bx * 32;

    for (int idx = t; idx < 32 * 27; idx += 256) {
        int b_l = idx / 27, kk = idx % 27;
        int k = kk / 3, c = kk % 3;
        float gv = coeff[(size_t)(g * 32 + b_l) * CST + 227 + c * 9 + k];
        if (k == 0) gv += 0.8f;
        sg[b_l * 27 + k * 3 + c] = gv;
    }
    __syncthreads();

    int vslot = t >> 5, b_l = t & 31;
    int b = g * 32 + b_l;
    #pragma unroll
    for (int it = 0; it < 4; it++) {
        int v_l = vslot + it * 8;
        int v = v0 + v_l;
        if (v < NV_) {
            const int4* pb4 = reinterpret_cast<const int4*>(g_pbuf + v * 8);
            int4 pa = pb4[0], pbv = pb4[1];
            int f[8] = {pa.x, pa.y, pa.z, pa.w, pbv.x, pbv.y, pbv.z, pbv.w};
            float fx[8], fy[8], fz[8];
            #pragma unroll
            for (int i = 0; i < 8; i++) {
                const __half* fn = g_face_norm + (size_t)(f[i] * 3) * B_ + b;
                fx[i] = __half2float(fn[0]);
                fy[i] = __half2float(fn[B_]);
                fz[i] = __half2float(fn[2 * B_]);
            }
            float sx = 0.f, sy = 0.f, sz = 0.f;
            #pragma unroll
            for (int i = 0; i < 8; i++) { sx += fx[i]; sy += fy[i]; sz += fz[i]; }
            float inv = rsqrtf(sx * sx + sy * sy + sz * sz);
            float nx = sx * inv, ny = sy * inv, nz = sz * inv;

            float Y[9];
            Y[0] = A0C0;
            Y[1] = -A1C1 * ny;
            Y[2] =  A1C1 * nz;
            Y[3] = -A1C1 * nx;
            Y[4] =  A2C2 * nx * ny;
            Y[5] = -A2C2 * ny * nz;
            Y[6] =  A2C2D0 * (3.f * nz * nz - 1.f);
            Y[7] = -A2C2 * nx * nz;
            Y[8] =  A2C2H * (nx * nx - ny * ny);

            const float* tx = g_tex + (size_t)(v * 3) * B_ + b;
            #pragma unroll
            for (int c = 0; c < 3; c++) {
                float l = 0.f;
                #pragma unroll
                for (int k = 0; k < 9; k++) l = fmaf(Y[k], sg[b_l * 27 + k * 3 + c], l);
                float col = tx[(size_t)c * B_] * l * (1.f / 255.f);
                sc[(v_l * 3 + c) * 33 + b_l] = fminf(fmaxf(col, 0.f), 1.f);
            }
        }
    }
    __syncthreads();

    int b_l2 = t >> 3, j = t & 7;
    int b2 = g * 32 + b_l2;
    #pragma unroll
    for (int w = 0; w < 4; w++) {
        int v_l = j * 4 + w;
        int v = v0 + v_l;
        if (v < NV_) {
            float* o = dout + OUT_COLOR + (size_t)b2 * NR_ + (size_t)v * 3;
            o[0] = sc[(v_l * 3 + 0) * 33 + b_l2];
            o[1] = sc[(v_l * 3 + 1) * 33 + b_l2];
            o[2] = sc[(v_l * 3 + 2) * 33 + b_l2];
        }
    }
}

__device__ __forceinline__ void tail_block(int bx, float* __restrict__ dout)
{
    int i = bx * 256 + threadIdx.x;
    const int LM_N = B_ * NK_ * 3;
    if (i < LM_N) {
        int d = i % 3, r = i / 3;
        int k = r % NK_, b = r / NK_;
        int v = g_kp[k];
        dout[OUT_LM + i] = dout[(size_t)b * NR_ + (size_t)v * 3 + d];
    } else {
        int q = i - LM_N;
        if (q < NF_ * 3) dout[OUT_TRI + q] = (float)g_tri[q];
    }
}

// ============================================================
// k_mix1: proj blocks + fn(group 0) + fn(group 1)
// ============================================================
__global__ void k_mix1(const float* __restrict__ coeff, float* __restrict__ dout)
{
    __shared__ __align__(16) float sm[3584];
    int bx = blockIdx.x;
    if (bx < NPROJ) {
        proj_block(bx, coeff, dout, sm);
    } else if (bx < NPROJ + NFN) {
        fn_block(bx - NPROJ, 0);
    } else {
        fn_block(bx - NPROJ - NFN, 1);
    }
}

// k_stage(G): color(2G) + color(2G+1) + fn(2G+2) + fn(2G+3)
__global__ __launch_bounds__(256, 4) void k_stage(
    int G, const float* __restrict__ coeff, float* __restrict__ dout)
{
    __shared__ __align__(16) float sm[4096];
    int bx = blockIdx.x;
    if (bx < NCOL) {
        color_block(bx, 2 * G, coeff, dout, sm);
    } else if (bx < 2 * NCOL) {
        color_block(bx - NCOL, 2 * G + 1, coeff, dout, sm);
    } else if (bx < 2 * NCOL + NFN) {
        if (G < 3) fn_block(bx - 2 * NCOL, 2 * G + 2);
        else       tail_block(bx - 2 * NCOL, dout);
    } else if (bx < 2 * NCOL + 2 * NFN) {
        if (G < 3) fn_block(bx - 2 * NCOL - NFN, 2 * G + 3);
    }
}

// ============================================================
extern "C" void kernel_launch(void* const* d_in, const int* in_sizes, int n_in,
                              void* d_out, int out_size)
{
    (void)in_sizes; (void)n_in; (void)out_size;
    const float* coeff     = (const float*)d_in[0];
    const float* meanshape = (const float*)d_in[1];
    const float* idBase    = (const float*)d_in[2];
    const float* exBase    = (const float*)d_in[3];
    const float* meantex   = (const float*)d_in[4];
    const float* texBase   = (const float*)d_in[5];
    const void*  tri       = d_in[6];
    const void*  pbuf      = d_in[7];
    const void*  kp        = d_in[8];
    float* dout = (float*)d_out;

    cudaStream_t s2;
    cudaStreamCreateWithFlags(&s2, cudaStreamNonBlocking);
    cudaEvent_t evA, evB;
    cudaEventCreateWithFlags(&evA, cudaEventDisableTiming);
    cudaEventCreateWithFlags(&evB, cudaEventDisableTiming);

    k_pre<<<257, 256>>>(tri, pbuf, kp, coeff, meanshape);
    cudaEventRecord(evA, 0);
    cudaStreamWaitEvent(s2, evA, 0);

    k_hmma_tex<<<NT64, 256, 0, s2>>>(texBase, meantex);
    k_hmma_shape<<<NT64, 256>>>(idBase, exBase, meanshape);
    k_mix1<<<NPROJ + 2 * NFN, 256>>>(coeff, dout);

    cudaEventRecord(evB, s2);
    cudaStreamWaitEvent(0, evB, 0);

    for (int G = 0; G < 3; G++)
        k_stage<<<2 * NCOL + 2 * NFN, 256>>>(G, coeff, dout);
    k_stage<<<2 * NCOL + NFN + NTAIL, 256>>>(3, coeff, dout);
}